// round 2
// baseline (speedup 1.0000x reference)
#include <cuda_runtime.h>
#include <cuda_bf16.h>
#include <math.h>

// Problem constants
#define T_TOK 2048
#define D_DIM 2048
#define HQ 32
#define HKV 4
#define HD 128
#define NE 64
#define TOPK 8
#define FF 768
#define NROWS (T_TOK*TOPK)   // 16384 gathered rows

// ---------------- scratch (device globals: allowed; no allocs) ----------------
__device__ float g_hnorm[T_TOK*D_DIM];
__device__ float g_q[T_TOK*HQ*HD];
__device__ float g_kb[T_TOK*HKV*HD];
__device__ float g_vb[T_TOK*HKV*HD];
__device__ float g_attno[T_TOK*HQ*HD];
__device__ float g_h2n[T_TOK*D_DIM];
__device__ float g_logits[T_TOK*NE];
__device__ int   g_tidx[T_TOK*TOPK];
__device__ float g_twt[T_TOK*TOPK];
__device__ int   g_counts[NE];
__device__ int   g_off[NE+1];
__device__ int   g_cursor[NE];
__device__ int   g_tok[NROWS];
__device__ int   g_crow[NROWS];
__device__ float g_rsc[NROWS];
__device__ float g_gbuf[NROWS*FF];
__device__ float g_ubuf[NROWS*FF];
__device__ float g_partial[(size_t)NROWS*D_DIM];

// ---------------- rmsnorm over D=2048 ----------------
__global__ __launch_bounds__(256) void rmsnorm_k(const float* __restrict__ x,
                                                 const float* __restrict__ sc,
                                                 float* __restrict__ y) {
    int row = blockIdx.x;
    const float* xr = x + (size_t)row * D_DIM;
    float ss = 0.f;
    for (int i = threadIdx.x; i < D_DIM; i += 256) { float v = xr[i]; ss += v * v; }
    for (int o = 16; o > 0; o >>= 1) ss += __shfl_xor_sync(0xffffffffu, ss, o);
    __shared__ float sw[8];
    if ((threadIdx.x & 31) == 0) sw[threadIdx.x >> 5] = ss;
    __syncthreads();
    float tot = 0.f;
#pragma unroll
    for (int i = 0; i < 8; i++) tot += sw[i];
    float inv = rsqrtf(tot * (1.f / D_DIM) + 1e-6f);
    float* yr = y + (size_t)row * D_DIM;
    for (int i = threadIdx.x; i < D_DIM; i += 256) yr[i] = xr[i] * inv * sc[i];
}

// ---------------- per-(token,head) rmsnorm + rope, in place ----------------
__global__ __launch_bounds__(128) void qknorm_rope_k(float* __restrict__ x,
                                                     const float* __restrict__ nsc,
                                                     const int* __restrict__ pos,
                                                     int H) {
    int t = blockIdx.x, h = blockIdx.y;
    float* xr = x + ((size_t)t * H + h) * HD;
    int d = threadIdx.x;  // 128 threads
    float v = xr[d];
    float ss = v * v;
    for (int o = 16; o > 0; o >>= 1) ss += __shfl_xor_sync(0xffffffffu, ss, o);
    __shared__ float sw[4];
    if ((d & 31) == 0) sw[d >> 5] = ss;
    __syncthreads();
    float tot = sw[0] + sw[1] + sw[2] + sw[3];
    float xn = v * rsqrtf(tot * (1.f / HD) + 1e-6f) * nsc[d];
    __shared__ float sx[HD];
    sx[d] = xn;
    __syncthreads();
    if (d < 64) {
        // inv_freq = ROPE_BASE^{-d/64} = exp(-d * ln(1e6)/64)
        float inv_freq = expf(-(float)d * 0.21586735246819178f);
        float ang = (float)pos[t] * inv_freq;
        float sn, cs;
        sincosf(ang, &sn, &cs);
        float x1 = sx[d], x2 = sx[d + 64];
        xr[d]      = x1 * cs - x2 * sn;
        xr[d + 64] = x2 * cs + x1 * sn;
    }
}

// ---------------- generic guarded SGEMM (128x128x8, 8x8/thread) ----------------
// Modes via nullable pointers:
//   eoff     : expert offsets[NE+1]; blockIdx.z = expert; B += e*K*N; rows local to expert
//   agather  : A row = agather[rb + r]  (else rb + r)
//   cscatter : C row = cscatter[rb + r] (else rb + r)
//   rscale   : C row scaled by rscale[rb + r]
//   addv     : C += addv[crow*N + col]  (residual add)
__global__ __launch_bounds__(256) void sgemm_k(
    const float* __restrict__ A, const float* __restrict__ B, float* __restrict__ C,
    int M, int N, int K,
    const int* __restrict__ eoff,
    const int* __restrict__ agather,
    const int* __restrict__ cscatter,
    const float* __restrict__ rscale,
    const float* __restrict__ addv) {
    __shared__ float As[8][128];
    __shared__ float Bs[8][128];

    int rb = 0, Me = M;
    const float* Bp = B;
    if (eoff) {
        int e = blockIdx.z;
        rb = eoff[e];
        Me = eoff[e + 1] - rb;
        Bp = B + (size_t)e * K * N;
    }
    int m0 = blockIdx.y * 128;
    if (m0 >= Me) return;
    int n0 = blockIdx.x * 128;

    int tid = threadIdx.x;
    int tx = tid & 15, ty = tid >> 4;

    // A load: one float4/thread: row tid>>1 (0..127), k-offset (tid&1)*4
    int a_i = tid >> 1;
    int a_j = (tid & 1) * 4;
    const float* Arow = nullptr;
    {
        int a_r = m0 + a_i;
        if (a_r < Me) {
            int ar = agather ? agather[rb + a_r] : (rb + a_r);
            Arow = A + (size_t)ar * K;
        }
    }
    // B load: row tid>>5 (0..7), col-offset (tid&31)*4
    int b_i = tid >> 5;
    int b_j = (tid & 31) * 4;
    bool bok = (n0 + b_j) < N;  // N is always a multiple of 4

    float acc[8][8];
#pragma unroll
    for (int a = 0; a < 8; a++)
#pragma unroll
        for (int b = 0; b < 8; b++) acc[a][b] = 0.f;

    for (int k0 = 0; k0 < K; k0 += 8) {
        float4 av = make_float4(0.f, 0.f, 0.f, 0.f);
        if (Arow) av = *(const float4*)(Arow + k0 + a_j);
        As[a_j + 0][a_i] = av.x;
        As[a_j + 1][a_i] = av.y;
        As[a_j + 2][a_i] = av.z;
        As[a_j + 3][a_i] = av.w;
        float4 bv = make_float4(0.f, 0.f, 0.f, 0.f);
        if (bok) bv = *(const float4*)(Bp + (size_t)(k0 + b_i) * N + n0 + b_j);
        *(float4*)&Bs[b_i][b_j] = bv;
        __syncthreads();
#pragma unroll
        for (int j = 0; j < 8; ++j) {
            float ra[8], rbv[8];
#pragma unroll
            for (int a = 0; a < 8; a++) ra[a] = As[j][ty * 8 + a];
#pragma unroll
            for (int b = 0; b < 8; b++) rbv[b] = Bs[j][tx * 8 + b];
#pragma unroll
            for (int a = 0; a < 8; a++)
#pragma unroll
                for (int b = 0; b < 8; b++) acc[a][b] += ra[a] * rbv[b];
        }
        __syncthreads();
    }

#pragma unroll
    for (int a = 0; a < 8; a++) {
        int r = m0 + ty * 8 + a;
        if (r < Me) {
            int cr = cscatter ? cscatter[rb + r] : (rb + r);
            float sc = rscale ? rscale[rb + r] : 1.0f;
            float* Crow = C + (size_t)cr * N;
            const float* addrow = addv ? (addv + (size_t)cr * N) : nullptr;
#pragma unroll
            for (int b = 0; b < 8; b++) {
                int c = n0 + tx * 8 + b;
                if (c < N) Crow[c] = acc[a][b] * sc + (addrow ? addrow[c] : 0.f);
            }
        }
    }
}

// ---------------- causal GQA attention: warp handles 4 query rows ----------------
__global__ __launch_bounds__(128) void attn_k(const float* __restrict__ Q,
                                              const float* __restrict__ Kb,
                                              const float* __restrict__ Vb,
                                              float* __restrict__ O) {
    int w = threadIdx.x >> 5, lane = threadIdx.x & 31;
    int qh = blockIdx.y;
    int kvh = qh >> 3;
    int t0 = blockIdx.x * 16 + w * 4;
    const float scale = 0.08838834764831845f;  // 128^-0.5

    float4 q[4], o[4];
    float m[4], l[4];
#pragma unroll
    for (int i = 0; i < 4; i++) {
        q[i] = *(const float4*)(Q + ((size_t)(t0 + i) * HQ + qh) * HD + lane * 4);
        o[i] = make_float4(0.f, 0.f, 0.f, 0.f);
        m[i] = -1e30f;
        l[i] = 0.f;
    }
    int jmax = t0 + 3;
    for (int j = 0; j <= jmax; ++j) {
        float4 kv = *(const float4*)(Kb + ((size_t)j * HKV + kvh) * HD + lane * 4);
        float4 vv = *(const float4*)(Vb + ((size_t)j * HKV + kvh) * HD + lane * 4);
#pragma unroll
        for (int i = 0; i < 4; i++) {
            float s = q[i].x * kv.x + q[i].y * kv.y + q[i].z * kv.z + q[i].w * kv.w;
            for (int off = 16; off > 0; off >>= 1) s += __shfl_xor_sync(0xffffffffu, s, off);
            s *= scale;
            if (j <= t0 + i) {
                float mn = fmaxf(m[i], s);
                float corr = __expf(m[i] - mn);
                float p = __expf(s - mn);
                l[i] = l[i] * corr + p;
                m[i] = mn;
                o[i].x = o[i].x * corr + p * vv.x;
                o[i].y = o[i].y * corr + p * vv.y;
                o[i].z = o[i].z * corr + p * vv.z;
                o[i].w = o[i].w * corr + p * vv.w;
            }
        }
    }
#pragma unroll
    for (int i = 0; i < 4; i++) {
        float inv = 1.0f / l[i];
        float4 r = make_float4(o[i].x * inv, o[i].y * inv, o[i].z * inv, o[i].w * inv);
        *(float4*)(O + ((size_t)(t0 + i) * HQ + qh) * HD + lane * 4) = r;
    }
}

// ---------------- router top-8 (warp per token, 64 logits) ----------------
__global__ __launch_bounds__(256) void topk_k(const float* __restrict__ logits,
                                              int* __restrict__ idx,
                                              float* __restrict__ wts) {
    int t = blockIdx.x * 8 + (threadIdx.x >> 5);
    int lane = threadIdx.x & 31;
    if (t >= T_TOK) return;
    const float* lr = logits + (size_t)t * NE;
    float v0 = lr[lane], v1 = lr[lane + 32];
    float selv[TOPK];
    int seli[TOPK];
    for (int s = 0; s < TOPK; s++) {
        float bv = v0;
        int bi = lane;
        if (v1 > bv) { bv = v1; bi = lane + 32; }
        for (int off = 16; off > 0; off >>= 1) {
            float ov = __shfl_xor_sync(0xffffffffu, bv, off);
            int oi = __shfl_xor_sync(0xffffffffu, bi, off);
            if (ov > bv || (ov == bv && oi < bi)) { bv = ov; bi = oi; }
        }
        selv[s] = bv;
        seli[s] = bi;
        if (bi == lane) v0 = -1e30f;
        if (bi == lane + 32) v1 = -1e30f;
    }
    if (lane == 0) {
        // softmax Z cancels in the renormalization: w_s = exp(l_s - max)/sum
        float mx = selv[0];
        float e[TOPK], sum = 0.f;
        for (int s = 0; s < TOPK; s++) { e[s] = __expf(selv[s] - mx); sum += e[s]; }
        float inv = 1.f / sum;
        for (int s = 0; s < TOPK; s++) {
            idx[t * TOPK + s] = seli[s];
            wts[t * TOPK + s] = e[s] * inv;
        }
    }
}

// ---------------- routing plumbing ----------------
__global__ void zero64_k(int* c) { if (threadIdx.x < NE) c[threadIdx.x] = 0; }

__global__ void count_k(const int* __restrict__ idx, int* __restrict__ counts) {
    int i = blockIdx.x * blockDim.x + threadIdx.x;
    if (i < T_TOK * TOPK) atomicAdd(&counts[idx[i]], 1);
}

__global__ void scan_k(const int* __restrict__ counts, int* __restrict__ off,
                       int* __restrict__ cursor) {
    if (threadIdx.x == 0) {
        int s = 0;
        for (int e = 0; e < NE; e++) { off[e] = s; cursor[e] = s; s += counts[e]; }
        off[NE] = s;
    }
}

__global__ void fill_k(const int* __restrict__ idx, const float* __restrict__ wts,
                       int* __restrict__ cursor, int* __restrict__ tok,
                       int* __restrict__ crow, float* __restrict__ rsc) {
    int i = blockIdx.x * blockDim.x + threadIdx.x;
    if (i < T_TOK * TOPK) {
        int t = i >> 3;
        int e = idx[i];
        int p = atomicAdd(&cursor[e], 1);
        tok[p] = t;
        crow[p] = i;  // == t*TOPK + slot
        rsc[p] = wts[i];
    }
}

// ---------------- silu(g) * u, in place into g ----------------
__global__ void silumul_k(float* __restrict__ g, const float* __restrict__ u, int n) {
    int i = blockIdx.x * blockDim.x + threadIdx.x;
    if (i < n) {
        float x = g[i];
        g[i] = (x / (1.f + __expf(-x))) * u[i];
    }
}

// ---------------- combine 8 slots per token (deterministic) ----------------
__global__ void combine_k(const float* __restrict__ part, float* __restrict__ out) {
    int i = blockIdx.x * blockDim.x + threadIdx.x;
    if (i < T_TOK * D_DIM) {
        int t = i >> 11;       // /2048
        int d = i & 2047;
        float s = 0.f;
#pragma unroll
        for (int sl = 0; sl < TOPK; sl++)
            s += part[((size_t)(t * TOPK + sl)) * D_DIM + d];
        out[i] = s;
    }
}

// ---------------- launch ----------------
extern "C" void kernel_launch(void* const* d_in, const int* in_sizes, int n_in,
                              void* d_out, int out_size) {
    const int*   positions = (const int*)d_in[0];
    const float* hidden    = (const float*)d_in[1];
    const float* in_ln     = (const float*)d_in[2];
    const float* post_ln   = (const float*)d_in[3];
    const float* qns       = (const float*)d_in[4];
    const float* kns       = (const float*)d_in[5];
    const float* wq        = (const float*)d_in[6];
    const float* wk        = (const float*)d_in[7];
    const float* wv        = (const float*)d_in[8];
    const float* wo        = (const float*)d_in[9];
    const float* wr        = (const float*)d_in[10];
    const float* wg        = (const float*)d_in[11];
    const float* wu        = (const float*)d_in[12];
    const float* wd        = (const float*)d_in[13];

    float* outp   = (float*)d_out;                 // [T, D] moe output
    float* residp = outp + (size_t)T_TOK * D_DIM;  // [T, D] residual output

    float *hnorm, *qb, *kb, *vb, *attno, *h2n, *logits, *twt, *rsc, *gbuf, *ubuf, *part;
    int *tidx, *counts, *off, *cursor, *tok, *crow;
    cudaGetSymbolAddress((void**)&hnorm, g_hnorm);
    cudaGetSymbolAddress((void**)&qb, g_q);
    cudaGetSymbolAddress((void**)&kb, g_kb);
    cudaGetSymbolAddress((void**)&vb, g_vb);
    cudaGetSymbolAddress((void**)&attno, g_attno);
    cudaGetSymbolAddress((void**)&h2n, g_h2n);
    cudaGetSymbolAddress((void**)&logits, g_logits);
    cudaGetSymbolAddress((void**)&tidx, g_tidx);
    cudaGetSymbolAddress((void**)&twt, g_twt);
    cudaGetSymbolAddress((void**)&counts, g_counts);
    cudaGetSymbolAddress((void**)&off, g_off);
    cudaGetSymbolAddress((void**)&cursor, g_cursor);
    cudaGetSymbolAddress((void**)&tok, g_tok);
    cudaGetSymbolAddress((void**)&crow, g_crow);
    cudaGetSymbolAddress((void**)&rsc, g_rsc);
    cudaGetSymbolAddress((void**)&gbuf, g_gbuf);
    cudaGetSymbolAddress((void**)&ubuf, g_ubuf);
    cudaGetSymbolAddress((void**)&part, g_partial);

    // 1. pre-attention rmsnorm
    rmsnorm_k<<<T_TOK, 256>>>(hidden, in_ln, hnorm);

    // 2. QKV projections
    sgemm_k<<<dim3(32, 16, 1), 256>>>(hnorm, wq, qb, T_TOK, HQ * HD, D_DIM,
                                      nullptr, nullptr, nullptr, nullptr, nullptr);
    sgemm_k<<<dim3(4, 16, 1), 256>>>(hnorm, wk, kb, T_TOK, HKV * HD, D_DIM,
                                     nullptr, nullptr, nullptr, nullptr, nullptr);
    sgemm_k<<<dim3(4, 16, 1), 256>>>(hnorm, wv, vb, T_TOK, HKV * HD, D_DIM,
                                     nullptr, nullptr, nullptr, nullptr, nullptr);

    // 3. QK rmsnorm + rope (in place)
    qknorm_rope_k<<<dim3(T_TOK, HQ), 128>>>(qb, qns, positions, HQ);
    qknorm_rope_k<<<dim3(T_TOK, HKV), 128>>>(kb, kns, positions, HKV);

    // 4. causal GQA attention
    attn_k<<<dim3(T_TOK / 16, HQ), 128>>>(qb, kb, vb, attno);

    // 5. O projection + residual add -> residual output (second half of d_out)
    sgemm_k<<<dim3(16, 16, 1), 256>>>(attno, wo, residp, T_TOK, D_DIM, HQ * HD,
                                      nullptr, nullptr, nullptr, nullptr, hidden);

    // 6. post-attention rmsnorm
    rmsnorm_k<<<T_TOK, 256>>>(residp, post_ln, h2n);

    // 7. router logits + top-8
    sgemm_k<<<dim3(1, 16, 1), 256>>>(h2n, wr, logits, T_TOK, NE, D_DIM,
                                     nullptr, nullptr, nullptr, nullptr, nullptr);
    topk_k<<<T_TOK / 8, 256>>>(logits, tidx, twt);

    // 8. build per-expert token lists
    zero64_k<<<1, 64>>>(counts);
    count_k<<<(T_TOK * TOPK + 255) / 256, 256>>>(tidx, counts);
    scan_k<<<1, 32>>>(counts, off, cursor);
    fill_k<<<(T_TOK * TOPK + 255) / 256, 256>>>(tidx, twt, cursor, tok, crow, rsc);

    // 9. expert up/gate gather-GEMMs: [n_e, 2048] x [2048, 768]
    sgemm_k<<<dim3(6, 16, 64), 256>>>(h2n, wg, gbuf, T_TOK, FF, D_DIM,
                                      off, tok, nullptr, nullptr, nullptr);
    sgemm_k<<<dim3(6, 16, 64), 256>>>(h2n, wu, ubuf, T_TOK, FF, D_DIM,
                                      off, tok, nullptr, nullptr, nullptr);

    // 10. act = silu(g) * u
    silumul_k<<<(NROWS * FF + 255) / 256, 256>>>(gbuf, ubuf, NROWS * FF);

    // 11. expert down scatter-GEMM: [n_e, 768] x [768, 2048] -> partial[(t,slot)]
    sgemm_k<<<dim3(16, 16, 64), 256>>>(gbuf, wd, part, T_TOK, D_DIM, FF,
                                       off, nullptr, crow, rsc, nullptr);

    // 12. deterministic combine over 8 slots -> moe output (first half of d_out)
    combine_k<<<(T_TOK * D_DIM + 255) / 256, 256>>>(part, outp);
}

// round 4
// speedup vs baseline: 1.5169x; 1.5169x over previous
#include <cuda_runtime.h>
#include <cuda_bf16.h>
#include <math.h>
#include <stdint.h>

// Problem constants
#define T_TOK 2048
#define D_DIM 2048
#define HQ 32
#define HKV 4
#define HD 128
#define NE 64
#define TOPK 8
#define FF 768
#define NROWS (T_TOK*TOPK)
#define QKV_N (HQ*HD + 2*HKV*HD)   // 5120
#define GU_N  (2*FF)               // 1536

typedef __nv_bfloat16 bf16;

__device__ __forceinline__ uint32_t smem_u32(const void* p) {
    uint32_t a;
    asm("{ .reg .u64 t; cvta.to.shared.u64 t, %1; cvt.u32.u64 %0, t; }" : "=r"(a) : "l"(p));
    return a;
}
__device__ __forceinline__ uint32_t lds32(uint32_t addr) {
    uint32_t v;
    asm volatile("ld.shared.b32 %0, [%1];" : "=r"(v) : "r"(addr));
    return v;
}
__device__ __forceinline__ void cp16(uint32_t dst, const void* src, int sz) {
    asm volatile("cp.async.cg.shared.global [%0], [%1], 16, %2;"
                 :: "r"(dst), "l"(src), "r"(sz));
}
__device__ __forceinline__ void mma_bf16(float* d, const uint32_t* a, uint32_t b0, uint32_t b1) {
    asm volatile("mma.sync.aligned.m16n8k16.row.col.f32.bf16.bf16.f32 "
                 "{%0,%1,%2,%3}, {%4,%5,%6,%7}, {%8,%9}, {%0,%1,%2,%3};"
                 : "+f"(d[0]), "+f"(d[1]), "+f"(d[2]), "+f"(d[3])
                 : "r"(a[0]), "r"(a[1]), "r"(a[2]), "r"(a[3]), "r"(b0), "r"(b1));
}
__device__ __forceinline__ void split_bf16(float x, bf16& h, bf16& l) {
    h = __float2bfloat16(x);
    l = __float2bfloat16(x - __bfloat162float(h));
}

// ===================== scratch =====================
__device__ bf16 g_qkvT_hi[(size_t)QKV_N * D_DIM];
__device__ bf16 g_qkvT_lo[(size_t)QKV_N * D_DIM];
__device__ bf16 g_woT_hi[(size_t)D_DIM * (HQ*HD)];
__device__ bf16 g_woT_lo[(size_t)D_DIM * (HQ*HD)];
__device__ bf16 g_wguT_hi[(size_t)NE * GU_N * D_DIM];
__device__ bf16 g_wguT_lo[(size_t)NE * GU_N * D_DIM];
__device__ bf16 g_wdT_hi[(size_t)NE * D_DIM * FF];
__device__ bf16 g_wdT_lo[(size_t)NE * D_DIM * FF];
__device__ bf16 g_hn_hi[(size_t)T_TOK * D_DIM];
__device__ bf16 g_hn_lo[(size_t)T_TOK * D_DIM];
__device__ float g_qkv[(size_t)T_TOK * QKV_N];
__device__ bf16 g_ao_hi[(size_t)T_TOK * (HQ*HD)];
__device__ bf16 g_ao_lo[(size_t)T_TOK * (HQ*HD)];
__device__ float g_h2n[(size_t)T_TOK * D_DIM];
__device__ bf16 g_h2n_hi[(size_t)T_TOK * D_DIM];
__device__ bf16 g_h2n_lo[(size_t)T_TOK * D_DIM];
__device__ float g_logits[T_TOK*NE];
__device__ int   g_tidx[T_TOK*TOPK];
__device__ float g_twt[T_TOK*TOPK];
__device__ int   g_counts[NE];
__device__ int   g_off[NE+1];
__device__ int   g_cursor[NE];
__device__ int   g_tok[NROWS];
__device__ int   g_crow[NROWS];
__device__ float g_rsc[NROWS];
__device__ float g_gu[(size_t)NROWS * GU_N];
__device__ bf16 g_act_hi[(size_t)NROWS * FF];
__device__ bf16 g_act_lo[(size_t)NROWS * FF];
__device__ float g_part[(size_t)NROWS * D_DIM];

// ===================== transpose + bf16 split =====================
__global__ __launch_bounds__(256) void transpose_split_k(
    const float* __restrict__ in, bf16* __restrict__ hi, bf16* __restrict__ lo,
    int R, int C, int ldout, int rowOff, size_t inStrideZ, size_t outStrideZ) {
    int z = blockIdx.z;
    in += (size_t)z * inStrideZ;
    hi += (size_t)z * outStrideZ;
    lo += (size_t)z * outStrideZ;
    __shared__ float t[32][33];
    int c0 = blockIdx.x * 32, r0 = blockIdx.y * 32;
    int tx = threadIdx.x & 31, ty = threadIdx.x >> 5;
    for (int j = ty; j < 32; j += 8) t[j][tx] = in[(size_t)(r0 + j) * C + c0 + tx];
    __syncthreads();
    for (int j = ty; j < 32; j += 8) {
        float v = t[tx][j];
        bf16 h, l;
        split_bf16(v, h, l);
        size_t o = (size_t)(rowOff + c0 + j) * ldout + r0 + tx;
        hi[o] = h;
        lo[o] = l;
    }
}

// ===================== rmsnorm (+ optional fp32 full, + bf16 split) =====================
__global__ __launch_bounds__(256) void rmsnorm_split_k(
    const float* __restrict__ x, const float* __restrict__ sc,
    float* __restrict__ full, bf16* __restrict__ hi, bf16* __restrict__ lo) {
    int row = blockIdx.x;
    const float* xr = x + (size_t)row * D_DIM;
    float ss = 0.f;
    for (int i = threadIdx.x; i < D_DIM; i += 256) { float v = xr[i]; ss += v * v; }
    for (int o = 16; o > 0; o >>= 1) ss += __shfl_xor_sync(0xffffffffu, ss, o);
    __shared__ float sw[8];
    if ((threadIdx.x & 31) == 0) sw[threadIdx.x >> 5] = ss;
    __syncthreads();
    float tot = 0.f;
#pragma unroll
    for (int i = 0; i < 8; i++) tot += sw[i];
    float inv = rsqrtf(tot * (1.f / D_DIM) + 1e-6f);
    size_t base = (size_t)row * D_DIM;
    for (int i = threadIdx.x; i < D_DIM; i += 256) {
        float v = xr[i] * inv * sc[i];
        if (full) full[base + i] = v;
        bf16 h, l;
        split_bf16(v, h, l);
        hi[base + i] = h;
        lo[base + i] = l;
    }
}

// ===================== qk norm + rope on packed qkv =====================
__global__ __launch_bounds__(128) void qknorm_rope_k(float* __restrict__ qkv,
                                                     const float* __restrict__ qns,
                                                     const float* __restrict__ kns,
                                                     const int* __restrict__ pos) {
    int t = blockIdx.x, h = blockIdx.y;
    float* xr;
    const float* nsc;
    if (h < HQ) { xr = qkv + (size_t)t * QKV_N + h * HD; nsc = qns; }
    else        { xr = qkv + (size_t)t * QKV_N + HQ*HD + (h - HQ) * HD; nsc = kns; }
    int d = threadIdx.x;
    float v = xr[d];
    float ss = v * v;
    for (int o = 16; o > 0; o >>= 1) ss += __shfl_xor_sync(0xffffffffu, ss, o);
    __shared__ float sw[4];
    if ((d & 31) == 0) sw[d >> 5] = ss;
    __syncthreads();
    float tot = sw[0] + sw[1] + sw[2] + sw[3];
    float xn = v * rsqrtf(tot * (1.f / HD) + 1e-6f) * nsc[d];
    __shared__ float sx[HD];
    sx[d] = xn;
    __syncthreads();
    if (d < 64) {
        float inv_freq = expf(-(float)d * 0.21586735246819178f);
        float ang = (float)pos[t] * inv_freq;
        float sn, cs;
        sincosf(ang, &sn, &cs);
        float x1 = sx[d], x2 = sx[d + 64];
        xr[d]      = x1 * cs - x2 * sn;
        xr[d + 64] = x2 * cs + x1 * sn;
    }
}

// ===================== causal GQA attention (fp32) -> split bf16 out =====================
__global__ __launch_bounds__(128) void attn_k(const float* __restrict__ qkv,
                                              bf16* __restrict__ Ohi,
                                              bf16* __restrict__ Olo) {
    int w = threadIdx.x >> 5, lane = threadIdx.x & 31;
    int qh = blockIdx.y;
    int kvh = qh >> 3;
    int t0 = blockIdx.x * 16 + w * 4;
    const float scale = 0.08838834764831845f;

    float4 q[4], o[4];
    float m[4], l[4];
#pragma unroll
    for (int i = 0; i < 4; i++) {
        q[i] = *(const float4*)(qkv + (size_t)(t0 + i) * QKV_N + qh * HD + lane * 4);
        o[i] = make_float4(0.f, 0.f, 0.f, 0.f);
        m[i] = -1e30f;
        l[i] = 0.f;
    }
    const float* kbase = qkv + HQ*HD + kvh * HD + lane * 4;
    const float* vbase = qkv + HQ*HD + HKV*HD + kvh * HD + lane * 4;
    int jmax = t0 + 3;
    for (int j = 0; j <= jmax; ++j) {
        float4 kv = *(const float4*)(kbase + (size_t)j * QKV_N);
        float4 vv = *(const float4*)(vbase + (size_t)j * QKV_N);
#pragma unroll
        for (int i = 0; i < 4; i++) {
            float s = q[i].x * kv.x + q[i].y * kv.y + q[i].z * kv.z + q[i].w * kv.w;
            for (int off = 16; off > 0; off >>= 1) s += __shfl_xor_sync(0xffffffffu, s, off);
            s *= scale;
            if (j <= t0 + i) {
                float mn = fmaxf(m[i], s);
                float corr = __expf(m[i] - mn);
                float p = __expf(s - mn);
                l[i] = l[i] * corr + p;
                m[i] = mn;
                o[i].x = o[i].x * corr + p * vv.x;
                o[i].y = o[i].y * corr + p * vv.y;
                o[i].z = o[i].z * corr + p * vv.z;
                o[i].w = o[i].w * corr + p * vv.w;
            }
        }
    }
#pragma unroll
    for (int i = 0; i < 4; i++) {
        float inv = 1.0f / l[i];
        float vals[4] = {o[i].x * inv, o[i].y * inv, o[i].z * inv, o[i].w * inv};
        size_t ob = (size_t)(t0 + i) * (HQ*HD) + qh * HD + lane * 4;
#pragma unroll
        for (int c = 0; c < 4; c++) {
            bf16 h, l2;
            split_bf16(vals[c], h, l2);
            Ohi[ob + c] = h;
            Olo[ob + c] = l2;
        }
    }
}

// ===================== HMMA bf16x3 GEMM =====================
// C[M,N] = A @ B (B given as B^T [N,K], K-major). 128x128 tile, chunk K=32,
// cp.async double-buffered. smem row stride 80B (bank-conflict-free).
// Layout per buffer (40960B): Ahi @0, Alo @10240, Bhi @20480, Blo @30720.
__global__ __launch_bounds__(256) void mma_gemm_k(
    const bf16* __restrict__ Ahi, const bf16* __restrict__ Alo,
    const bf16* __restrict__ Bhi, const bf16* __restrict__ Blo,
    float* __restrict__ C, int ldc,
    int M, int N, int K,
    const int* __restrict__ eoff, const int* __restrict__ agather,
    const int* __restrict__ cscatter, const float* __restrict__ rscale,
    const float* __restrict__ addv) {
    int rb = 0, Me = M;
    const bf16* bh = Bhi;
    const bf16* bl = Blo;
    if (eoff) {
        int e = blockIdx.z;
        rb = eoff[e];
        Me = eoff[e + 1] - rb;
        bh += (size_t)e * N * K;
        bl += (size_t)e * N * K;
    }
    int m0 = blockIdx.y * 128;
    if (m0 >= Me) return;
    int n0 = blockIdx.x * 128;

    extern __shared__ char smem[];
    uint32_t sbase = smem_u32(smem);
    int tid = threadIdx.x;

    // cp.async assignments: 512 16B segs per array, 2 per thread
    int seg0 = tid * 2, seg1 = tid * 2 + 1;
    int r0 = seg0 >> 2, j0 = seg0 & 3;
    int r1 = seg1 >> 2, j1 = seg1 & 3;
    int am0 = m0 + r0, am1 = m0 + r1;
    int av0 = (am0 < Me) ? 16 : 0, av1 = (am1 < Me) ? 16 : 0;
    size_t ar0 = 0, ar1 = 0;
    if (av0) ar0 = (size_t)(agather ? agather[rb + am0] : (rb + am0)) * K;
    if (av1) ar1 = (size_t)(agather ? agather[rb + am1] : (rb + am1)) * K;
    size_t br0 = (size_t)(n0 + r0) * K, br1 = (size_t)(n0 + r1) * K;
    uint32_t dA0 = r0 * 80 + j0 * 16, dA1 = r1 * 80 + j1 * 16;

    auto issue_chunk = [&](int c, int buf) {
        uint32_t sb = sbase + buf * 40960;
        size_t kof = (size_t)c * 32;
        cp16(sb + dA0,         Ahi + ar0 + kof + j0 * 8, av0);
        cp16(sb + dA1,         Ahi + ar1 + kof + j1 * 8, av1);
        cp16(sb + 10240 + dA0, Alo + ar0 + kof + j0 * 8, av0);
        cp16(sb + 10240 + dA1, Alo + ar1 + kof + j1 * 8, av1);
        cp16(sb + 20480 + dA0, bh + br0 + kof + j0 * 8, 16);
        cp16(sb + 20480 + dA1, bh + br1 + kof + j1 * 8, 16);
        cp16(sb + 30720 + dA0, bl + br0 + kof + j0 * 8, 16);
        cp16(sb + 30720 + dA1, bl + br1 + kof + j1 * 8, 16);
        asm volatile("cp.async.commit_group;");
    };

    int lane = tid & 31, warp = tid >> 5;
    int wm = warp >> 1, wn = warp & 1;
    int g = lane >> 2, t = lane & 3;

    float acc[2][8][4];
#pragma unroll
    for (int m = 0; m < 2; m++)
#pragma unroll
        for (int nt = 0; nt < 8; nt++)
#pragma unroll
            for (int i = 0; i < 4; i++) acc[m][nt][i] = 0.f;

    int nch = K / 32;
    issue_chunk(0, 0);
    if (nch > 1) issue_chunk(1, 1);

    for (int c = 0; c < nch; c++) {
        if (c + 1 < nch) asm volatile("cp.async.wait_group 1;");
        else             asm volatile("cp.async.wait_group 0;");
        __syncthreads();
        uint32_t sb = sbase + (c & 1) * 40960;
#pragma unroll
        for (int ks = 0; ks < 2; ks++) {
            uint32_t Ah[2][4], Al[2][4];
#pragma unroll
            for (int m = 0; m < 2; m++) {
                uint32_t ra = sb + (uint32_t)((wm * 32 + m * 16 + g) * 80 + ks * 32 + t * 4);
                Ah[m][0] = lds32(ra);
                Ah[m][1] = lds32(ra + 640);
                Ah[m][2] = lds32(ra + 16);
                Ah[m][3] = lds32(ra + 656);
                Al[m][0] = lds32(ra + 10240);
                Al[m][1] = lds32(ra + 10880);
                Al[m][2] = lds32(ra + 10256);
                Al[m][3] = lds32(ra + 10896);
            }
#pragma unroll
            for (int nt = 0; nt < 8; nt++) {
                uint32_t rbB = sb + 20480 + (uint32_t)((wn * 64 + nt * 8 + g) * 80 + ks * 32 + t * 4);
                uint32_t bh0 = lds32(rbB);
                uint32_t bh1 = lds32(rbB + 16);
                uint32_t bl0 = lds32(rbB + 10240);
                uint32_t bl1 = lds32(rbB + 10256);
#pragma unroll
                for (int m = 0; m < 2; m++) {
                    mma_bf16(acc[m][nt], Ah[m], bh0, bh1);
                    mma_bf16(acc[m][nt], Ah[m], bl0, bl1);
                    mma_bf16(acc[m][nt], Al[m], bh0, bh1);
                }
            }
        }
        __syncthreads();
        if (c + 2 < nch) issue_chunk(c + 2, c & 1);
    }

    // epilogue: direct global stores, row-guarded, with scatter/scale/residual
#pragma unroll
    for (int m = 0; m < 2; m++) {
        int rlow = m0 + wm * 32 + m * 16 + g;
        int rhigh = rlow + 8;
        int crl = 0, crh = 0;
        float scl = 1.f, sch = 1.f;
        bool okl = rlow < Me, okh = rhigh < Me;
        if (okl) {
            crl = cscatter ? cscatter[rb + rlow] : (rb + rlow);
            if (rscale) scl = rscale[rb + rlow];
        }
        if (okh) {
            crh = cscatter ? cscatter[rb + rhigh] : (rb + rhigh);
            if (rscale) sch = rscale[rb + rhigh];
        }
#pragma unroll
        for (int nt = 0; nt < 8; nt++) {
            int col = n0 + wn * 64 + nt * 8 + t * 2;
            float* a = acc[m][nt];
            if (okl) {
                size_t b = (size_t)crl * ldc + col;
                float v0 = a[0] * scl, v1 = a[1] * scl;
                if (addv) { v0 += addv[b]; v1 += addv[b + 1]; }
                C[b] = v0;
                C[b + 1] = v1;
            }
            if (okh) {
                size_t b = (size_t)crh * ldc + col;
                float v2 = a[2] * sch, v3 = a[3] * sch;
                if (addv) { v2 += addv[b]; v3 += addv[b + 1]; }
                C[b] = v2;
                C[b + 1] = v3;
            }
        }
    }
}

// ===================== SIMT sgemm (router only) =====================
__global__ __launch_bounds__(256) void sgemm_k(
    const float* __restrict__ A, const float* __restrict__ B, float* __restrict__ C,
    int M, int N, int K) {
    __shared__ float As[8][128];
    __shared__ float Bs[8][128];
    int m0 = blockIdx.y * 128;
    int n0 = blockIdx.x * 128;
    int tid = threadIdx.x;
    int tx = tid & 15, ty = tid >> 4;
    int a_i = tid >> 1;
    int a_j = (tid & 1) * 4;
    const float* Arow = A + (size_t)(m0 + a_i) * K;
    int b_i = tid >> 5;
    int b_j = (tid & 31) * 4;
    bool bok = (n0 + b_j) < N;
    float acc[8][8];
#pragma unroll
    for (int a = 0; a < 8; a++)
#pragma unroll
        for (int b = 0; b < 8; b++) acc[a][b] = 0.f;
    for (int k0 = 0; k0 < K; k0 += 8) {
        float4 av = *(const float4*)(Arow + k0 + a_j);
        As[a_j + 0][a_i] = av.x;
        As[a_j + 1][a_i] = av.y;
        As[a_j + 2][a_i] = av.z;
        As[a_j + 3][a_i] = av.w;
        float4 bv = make_float4(0.f, 0.f, 0.f, 0.f);
        if (bok) bv = *(const float4*)(B + (size_t)(k0 + b_i) * N + n0 + b_j);
        *(float4*)&Bs[b_i][b_j] = bv;
        __syncthreads();
#pragma unroll
        for (int j = 0; j < 8; ++j) {
            float ra[8], rbv[8];
#pragma unroll
            for (int a = 0; a < 8; a++) ra[a] = As[j][ty * 8 + a];
#pragma unroll
            for (int b = 0; b < 8; b++) rbv[b] = Bs[j][tx * 8 + b];
#pragma unroll
            for (int a = 0; a < 8; a++)
#pragma unroll
                for (int b = 0; b < 8; b++) acc[a][b] += ra[a] * rbv[b];
        }
        __syncthreads();
    }
#pragma unroll
    for (int a = 0; a < 8; a++) {
        int r = m0 + ty * 8 + a;
        float* Crow = C + (size_t)r * N;
#pragma unroll
        for (int b = 0; b < 8; b++) {
            int ccol = n0 + tx * 8 + b;
            if (ccol < N) Crow[ccol] = acc[a][b];
        }
    }
}

// ===================== router top-8 =====================
__global__ __launch_bounds__(256) void topk_k(const float* __restrict__ logits,
                                              int* __restrict__ idx,
                                              float* __restrict__ wts) {
    int t = blockIdx.x * 8 + (threadIdx.x >> 5);
    int lane = threadIdx.x & 31;
    if (t >= T_TOK) return;
    const float* lr = logits + (size_t)t * NE;
    float v0 = lr[lane], v1 = lr[lane + 32];
    float selv[TOPK];
    int seli[TOPK];
    for (int s = 0; s < TOPK; s++) {
        float bv = v0;
        int bi = lane;
        if (v1 > bv) { bv = v1; bi = lane + 32; }
        for (int off = 16; off > 0; off >>= 1) {
            float ov = __shfl_xor_sync(0xffffffffu, bv, off);
            int oi = __shfl_xor_sync(0xffffffffu, bi, off);
            if (ov > bv || (ov == bv && oi < bi)) { bv = ov; bi = oi; }
        }
        selv[s] = bv;
        seli[s] = bi;
        if (bi == lane) v0 = -1e30f;
        if (bi == lane + 32) v1 = -1e30f;
    }
    if (lane == 0) {
        float mx = selv[0];
        float e[TOPK], sum = 0.f;
        for (int s = 0; s < TOPK; s++) { e[s] = __expf(selv[s] - mx); sum += e[s]; }
        float inv = 1.f / sum;
        for (int s = 0; s < TOPK; s++) {
            idx[t * TOPK + s] = seli[s];
            wts[t * TOPK + s] = e[s] * inv;
        }
    }
}

// ===================== routing plumbing =====================
__global__ void zero64_k(int* c) { if (threadIdx.x < NE) c[threadIdx.x] = 0; }

__global__ void count_k(const int* __restrict__ idx, int* __restrict__ counts) {
    int i = blockIdx.x * blockDim.x + threadIdx.x;
    if (i < T_TOK * TOPK) atomicAdd(&counts[idx[i]], 1);
}

__global__ void scan_k(const int* __restrict__ counts, int* __restrict__ off,
                       int* __restrict__ cursor) {
    if (threadIdx.x == 0) {
        int s = 0;
        for (int e = 0; e < NE; e++) { off[e] = s; cursor[e] = s; s += counts[e]; }
        off[NE] = s;
    }
}

__global__ void fill_k(const int* __restrict__ idx, const float* __restrict__ wts,
                       int* __restrict__ cursor, int* __restrict__ tok,
                       int* __restrict__ crow, float* __restrict__ rsc) {
    int i = blockIdx.x * blockDim.x + threadIdx.x;
    if (i < T_TOK * TOPK) {
        int t = i >> 3;
        int e = idx[i];
        int p = atomicAdd(&cursor[e], 1);
        tok[p] = t;
        crow[p] = i;
        rsc[p] = wts[i];
    }
}

// ===================== silu(g)*u -> split bf16 act =====================
__global__ void silumul_split_k(const float* __restrict__ gu,
                                bf16* __restrict__ ahi, bf16* __restrict__ alo) {
    int i = blockIdx.x * blockDim.x + threadIdx.x;
    if (i < NROWS * FF) {
        int r = i / FF, j = i - r * FF;
        float g = gu[(size_t)r * GU_N + j];
        float u = gu[(size_t)r * GU_N + FF + j];
        float a = (g / (1.f + __expf(-g))) * u;
        bf16 h, l;
        split_bf16(a, h, l);
        ahi[i] = h;
        alo[i] = l;
    }
}

// ===================== combine 8 slots =====================
__global__ void combine_k(const float* __restrict__ part, float* __restrict__ out) {
    int i = blockIdx.x * blockDim.x + threadIdx.x;
    if (i < T_TOK * D_DIM) {
        int t = i >> 11;
        int d = i & 2047;
        float s = 0.f;
#pragma unroll
        for (int sl = 0; sl < TOPK; sl++)
            s += part[((size_t)(t * TOPK + sl)) * D_DIM + d];
        out[i] = s;
    }
}

// ===================== launch =====================
#define MMA_SMEM 81920

extern "C" void kernel_launch(void* const* d_in, const int* in_sizes, int n_in,
                              void* d_out, int out_size) {
    const int*   positions = (const int*)d_in[0];
    const float* hidden    = (const float*)d_in[1];
    const float* in_ln     = (const float*)d_in[2];
    const float* post_ln   = (const float*)d_in[3];
    const float* qns       = (const float*)d_in[4];
    const float* kns       = (const float*)d_in[5];
    const float* wq        = (const float*)d_in[6];
    const float* wk        = (const float*)d_in[7];
    const float* wv        = (const float*)d_in[8];
    const float* wo        = (const float*)d_in[9];
    const float* wr        = (const float*)d_in[10];
    const float* wg        = (const float*)d_in[11];
    const float* wu        = (const float*)d_in[12];
    const float* wd        = (const float*)d_in[13];

    float* outp   = (float*)d_out;
    float* residp = outp + (size_t)T_TOK * D_DIM;

    cudaFuncSetAttribute(mma_gemm_k, cudaFuncAttributeMaxDynamicSharedMemorySize, MMA_SMEM);

    bf16 *qkvT_hi, *qkvT_lo, *woT_hi, *woT_lo, *wguT_hi, *wguT_lo, *wdT_hi, *wdT_lo;
    bf16 *hn_hi, *hn_lo, *ao_hi, *ao_lo, *h2n_hi, *h2n_lo, *act_hi, *act_lo;
    float *qkv, *h2n, *logits, *twt, *rsc, *gu, *part;
    int *tidx, *counts, *off, *cursor, *tok, *crow;
    cudaGetSymbolAddress((void**)&qkvT_hi, g_qkvT_hi);
    cudaGetSymbolAddress((void**)&qkvT_lo, g_qkvT_lo);
    cudaGetSymbolAddress((void**)&woT_hi, g_woT_hi);
    cudaGetSymbolAddress((void**)&woT_lo, g_woT_lo);
    cudaGetSymbolAddress((void**)&wguT_hi, g_wguT_hi);
    cudaGetSymbolAddress((void**)&wguT_lo, g_wguT_lo);
    cudaGetSymbolAddress((void**)&wdT_hi, g_wdT_hi);
    cudaGetSymbolAddress((void**)&wdT_lo, g_wdT_lo);
    cudaGetSymbolAddress((void**)&hn_hi, g_hn_hi);
    cudaGetSymbolAddress((void**)&hn_lo, g_hn_lo);
    cudaGetSymbolAddress((void**)&qkv, g_qkv);
    cudaGetSymbolAddress((void**)&ao_hi, g_ao_hi);
    cudaGetSymbolAddress((void**)&ao_lo, g_ao_lo);
    cudaGetSymbolAddress((void**)&h2n, g_h2n);
    cudaGetSymbolAddress((void**)&h2n_hi, g_h2n_hi);
    cudaGetSymbolAddress((void**)&h2n_lo, g_h2n_lo);
    cudaGetSymbolAddress((void**)&logits, g_logits);
    cudaGetSymbolAddress((void**)&tidx, g_tidx);
    cudaGetSymbolAddress((void**)&twt, g_twt);
    cudaGetSymbolAddress((void**)&counts, g_counts);
    cudaGetSymbolAddress((void**)&off, g_off);
    cudaGetSymbolAddress((void**)&cursor, g_cursor);
    cudaGetSymbolAddress((void**)&tok, g_tok);
    cudaGetSymbolAddress((void**)&crow, g_crow);
    cudaGetSymbolAddress((void**)&rsc, g_rsc);
    cudaGetSymbolAddress((void**)&gu, g_gu);
    cudaGetSymbolAddress((void**)&act_hi, g_act_hi);
    cudaGetSymbolAddress((void**)&act_lo, g_act_lo);
    cudaGetSymbolAddress((void**)&part, g_part);

    // 0. weight transposes + bf16 splits (B^T layouts)
    transpose_split_k<<<dim3(HQ*HD/32, D_DIM/32, 1), 256>>>(wq, qkvT_hi, qkvT_lo,
        D_DIM, HQ*HD, D_DIM, 0, 0, 0);
    transpose_split_k<<<dim3(HKV*HD/32, D_DIM/32, 1), 256>>>(wk, qkvT_hi, qkvT_lo,
        D_DIM, HKV*HD, D_DIM, HQ*HD, 0, 0);
    transpose_split_k<<<dim3(HKV*HD/32, D_DIM/32, 1), 256>>>(wv, qkvT_hi, qkvT_lo,
        D_DIM, HKV*HD, D_DIM, HQ*HD + HKV*HD, 0, 0);
    transpose_split_k<<<dim3(D_DIM/32, (HQ*HD)/32, 1), 256>>>(wo, woT_hi, woT_lo,
        HQ*HD, D_DIM, HQ*HD, 0, 0, 0);
    transpose_split_k<<<dim3(FF/32, D_DIM/32, NE), 256>>>(wg, wguT_hi, wguT_lo,
        D_DIM, FF, D_DIM, 0, (size_t)D_DIM*FF, (size_t)GU_N*D_DIM);
    transpose_split_k<<<dim3(FF/32, D_DIM/32, NE), 256>>>(wu, wguT_hi, wguT_lo,
        D_DIM, FF, D_DIM, FF, (size_t)D_DIM*FF, (size_t)GU_N*D_DIM);
    transpose_split_k<<<dim3(D_DIM/32, FF/32, NE), 256>>>(wd, wdT_hi, wdT_lo,
        FF, D_DIM, FF, 0, (size_t)FF*D_DIM, (size_t)D_DIM*FF);

    // 1. pre-attention rmsnorm (split only)
    rmsnorm_split_k<<<T_TOK, 256>>>(hidden, in_ln, nullptr, hn_hi, hn_lo);

    // 2. fused QKV projection
    mma_gemm_k<<<dim3(QKV_N/128, T_TOK/128, 1), 256, MMA_SMEM>>>(
        hn_hi, hn_lo, qkvT_hi, qkvT_lo, qkv, QKV_N, T_TOK, QKV_N, D_DIM,
        nullptr, nullptr, nullptr, nullptr, nullptr);

    // 3. QK rmsnorm + rope
    qknorm_rope_k<<<dim3(T_TOK, HQ + HKV), 128>>>(qkv, qns, kns, positions);

    // 4. attention
    attn_k<<<dim3(T_TOK / 16, HQ), 128>>>(qkv, ao_hi, ao_lo);

    // 5. O projection + residual
    mma_gemm_k<<<dim3(D_DIM/128, T_TOK/128, 1), 256, MMA_SMEM>>>(
        ao_hi, ao_lo, woT_hi, woT_lo, residp, D_DIM, T_TOK, D_DIM, HQ*HD,
        nullptr, nullptr, nullptr, nullptr, hidden);

    // 6. post-attention rmsnorm
    rmsnorm_split_k<<<T_TOK, 256>>>(residp, post_ln, h2n, h2n_hi, h2n_lo);

    // 7. router + top-8
    sgemm_k<<<dim3(1, T_TOK/128, 1), 256>>>(h2n, wr, logits, T_TOK, NE, D_DIM);
    topk_k<<<T_TOK / 8, 256>>>(logits, tidx, twt);

    // 8. per-expert token lists
    zero64_k<<<1, 64>>>(counts);
    count_k<<<(T_TOK * TOPK + 255) / 256, 256>>>(tidx, counts);
    scan_k<<<1, 32>>>(counts, off, cursor);
    fill_k<<<(T_TOK * TOPK + 255) / 256, 256>>>(tidx, twt, cursor, tok, crow, rsc);

    // 9. fused gate+up gather-GEMM per expert
    mma_gemm_k<<<dim3(GU_N/128, 16, NE), 256, MMA_SMEM>>>(
        h2n_hi, h2n_lo, wguT_hi, wguT_lo, gu, GU_N, T_TOK, GU_N, D_DIM,
        off, tok, nullptr, nullptr, nullptr);

    // 10. silu(g)*u split
    silumul_split_k<<<(NROWS * FF + 255) / 256, 256>>>(gu, act_hi, act_lo);

    // 11. down scatter-GEMM per expert
    mma_gemm_k<<<dim3(D_DIM/128, 16, NE), 256, MMA_SMEM>>>(
        act_hi, act_lo, wdT_hi, wdT_lo, part, D_DIM, T_TOK, D_DIM, FF,
        off, nullptr, crow, rsc, nullptr);

    // 12. combine
    combine_k<<<(T_TOK * D_DIM + 255) / 256, 256>>>(part, outp);
}

// round 5
// speedup vs baseline: 2.6914x; 1.7743x over previous
#include <cuda_runtime.h>
#include <cuda_bf16.h>
#include <math.h>
#include <stdint.h>

// Problem constants
#define T_TOK 2048
#define D_DIM 2048
#define HQ 32
#define HKV 4
#define HD 128
#define NE 64
#define TOPK 8
#define FF 768
#define NROWS (T_TOK*TOPK)
#define QKV_N (HQ*HD + 2*HKV*HD)   // 5120
#define GU_N  (2*FF)               // 1536

typedef __nv_bfloat16 bf16;

__device__ __forceinline__ uint32_t smem_u32(const void* p) {
    uint32_t a;
    asm("{ .reg .u64 t; cvta.to.shared.u64 t, %1; cvt.u32.u64 %0, t; }" : "=r"(a) : "l"(p));
    return a;
}
__device__ __forceinline__ uint32_t lds32(uint32_t addr) {
    uint32_t v;
    asm volatile("ld.shared.b32 %0, [%1];" : "=r"(v) : "r"(addr));
    return v;
}
__device__ __forceinline__ void cp16(uint32_t dst, const void* src, int sz) {
    asm volatile("cp.async.cg.shared.global [%0], [%1], 16, %2;"
                 :: "r"(dst), "l"(src), "r"(sz));
}
__device__ __forceinline__ void mma_bf16(float* d, const uint32_t* a, uint32_t b0, uint32_t b1) {
    asm volatile("mma.sync.aligned.m16n8k16.row.col.f32.bf16.bf16.f32 "
                 "{%0,%1,%2,%3}, {%4,%5,%6,%7}, {%8,%9}, {%0,%1,%2,%3};"
                 : "+f"(d[0]), "+f"(d[1]), "+f"(d[2]), "+f"(d[3])
                 : "r"(a[0]), "r"(a[1]), "r"(a[2]), "r"(a[3]), "r"(b0), "r"(b1));
}
__device__ __forceinline__ void split_bf16(float x, bf16& h, bf16& l) {
    h = __float2bfloat16(x);
    l = __float2bfloat16(x - __bfloat162float(h));
}
__device__ __forceinline__ uint32_t pack_bf16(bf16 a, bf16 b) {
    return (uint32_t)__bfloat16_as_ushort(a) | ((uint32_t)__bfloat16_as_ushort(b) << 16);
}
__device__ __forceinline__ uint32_t pack2f(float a, float b) {
    return pack_bf16(__float2bfloat16(a), __float2bfloat16(b));
}
__device__ __forceinline__ uint32_t pack2f_lo(float a, float b, uint32_t hipair) {
    float ha = __bfloat162float(__ushort_as_bfloat16((unsigned short)(hipair & 0xFFFF)));
    float hb = __bfloat162float(__ushort_as_bfloat16((unsigned short)(hipair >> 16)));
    return pack_bf16(__float2bfloat16(a - ha), __float2bfloat16(b - hb));
}

// ===================== scratch =====================
__device__ bf16 g_qkvT_hi[(size_t)QKV_N * D_DIM];
__device__ bf16 g_qkvT_lo[(size_t)QKV_N * D_DIM];
__device__ bf16 g_woT_hi[(size_t)D_DIM * (HQ*HD)];
__device__ bf16 g_woT_lo[(size_t)D_DIM * (HQ*HD)];
__device__ bf16 g_wguT_hi[(size_t)NE * GU_N * D_DIM];
__device__ bf16 g_wguT_lo[(size_t)NE * GU_N * D_DIM];
__device__ bf16 g_wdT_hi[(size_t)NE * D_DIM * FF];
__device__ bf16 g_wdT_lo[(size_t)NE * D_DIM * FF];
__device__ bf16 g_hn_hi[(size_t)T_TOK * D_DIM];
__device__ bf16 g_hn_lo[(size_t)T_TOK * D_DIM];
__device__ float g_qkv[(size_t)T_TOK * QKV_N];
__device__ bf16 g_qh[(size_t)T_TOK * HQ*HD];
__device__ bf16 g_ql[(size_t)T_TOK * HQ*HD];
__device__ bf16 g_kh[(size_t)HKV * T_TOK * HD];
__device__ bf16 g_kl[(size_t)HKV * T_TOK * HD];
__device__ bf16 g_vth[(size_t)HKV * HD * T_TOK];
__device__ bf16 g_vtl[(size_t)HKV * HD * T_TOK];
__device__ bf16 g_ao_hi[(size_t)T_TOK * (HQ*HD)];
__device__ bf16 g_ao_lo[(size_t)T_TOK * (HQ*HD)];
__device__ float g_h2n[(size_t)T_TOK * D_DIM];
__device__ bf16 g_h2n_hi[(size_t)T_TOK * D_DIM];
__device__ bf16 g_h2n_lo[(size_t)T_TOK * D_DIM];
__device__ float g_logits[T_TOK*NE];
__device__ int   g_tidx[T_TOK*TOPK];
__device__ float g_twt[T_TOK*TOPK];
__device__ int   g_counts[NE];
__device__ int   g_off[NE+1];
__device__ int   g_cursor[NE];
__device__ int   g_tok[NROWS];
__device__ int   g_crow[NROWS];
__device__ float g_rsc[NROWS];
__device__ float g_gu[(size_t)NROWS * GU_N];
__device__ bf16 g_act_hi[(size_t)NROWS * FF];
__device__ bf16 g_act_lo[(size_t)NROWS * FF];
__device__ float g_part[(size_t)NROWS * D_DIM];

// ===================== transpose + bf16 split (vectorized stores) =====================
__global__ __launch_bounds__(256) void transpose_split_k(
    const float* __restrict__ in, bf16* __restrict__ hi, bf16* __restrict__ lo,
    int R, int C, int ldout, int rowOff, size_t inStrideZ, size_t outStrideZ) {
    int z = blockIdx.z;
    in += (size_t)z * inStrideZ;
    hi += (size_t)z * outStrideZ;
    lo += (size_t)z * outStrideZ;
    __shared__ float tb[32][33];
    int c0 = blockIdx.x * 32, r0 = blockIdx.y * 32;
    int tx = threadIdx.x & 31, ty = threadIdx.x >> 5;
    for (int j = ty; j < 32; j += 8) tb[j][tx] = in[(size_t)(r0 + j) * C + c0 + tx];
    __syncthreads();
    int px = threadIdx.x & 15, py = threadIdx.x >> 4;
    for (int j = py; j < 32; j += 16) {
        float v0 = tb[2 * px][j], v1 = tb[2 * px + 1][j];
        bf16 h0, l0, h1, l1;
        split_bf16(v0, h0, l0);
        split_bf16(v1, h1, l1);
        size_t o = (size_t)(rowOff + c0 + j) * ldout + r0 + 2 * px;
        *(uint32_t*)(hi + o) = pack_bf16(h0, h1);
        *(uint32_t*)(lo + o) = pack_bf16(l0, l1);
    }
}

// ===================== rmsnorm (+ optional fp32 full, + bf16 split) =====================
__global__ __launch_bounds__(256) void rmsnorm_split_k(
    const float* __restrict__ x, const float* __restrict__ sc,
    float* __restrict__ full, bf16* __restrict__ hi, bf16* __restrict__ lo) {
    int row = blockIdx.x;
    const float* xr = x + (size_t)row * D_DIM;
    float ss = 0.f;
    for (int i = threadIdx.x; i < D_DIM; i += 256) { float v = xr[i]; ss += v * v; }
    for (int o = 16; o > 0; o >>= 1) ss += __shfl_xor_sync(0xffffffffu, ss, o);
    __shared__ float sw[8];
    if ((threadIdx.x & 31) == 0) sw[threadIdx.x >> 5] = ss;
    __syncthreads();
    float tot = 0.f;
#pragma unroll
    for (int i = 0; i < 8; i++) tot += sw[i];
    float inv = rsqrtf(tot * (1.f / D_DIM) + 1e-6f);
    size_t base = (size_t)row * D_DIM;
    for (int i = threadIdx.x; i < D_DIM; i += 256) {
        float v = xr[i] * inv * sc[i];
        if (full) full[base + i] = v;
        bf16 h, l;
        split_bf16(v, h, l);
        hi[base + i] = h;
        lo[base + i] = l;
    }
}

// ===================== qk norm + rope -> split bf16 =====================
__global__ __launch_bounds__(128) void qknorm_rope_split_k(
    const float* __restrict__ qkv,
    const float* __restrict__ qns, const float* __restrict__ kns,
    const int* __restrict__ pos,
    bf16* __restrict__ qh, bf16* __restrict__ ql,
    bf16* __restrict__ kh, bf16* __restrict__ kl) {
    int t = blockIdx.x, h = blockIdx.y;  // 0..31 q, 32..35 k
    bool isq = h < HQ;
    const float* xr;
    const float* nsc;
    if (isq) { xr = qkv + (size_t)t * QKV_N + h * HD; nsc = qns; }
    else     { xr = qkv + (size_t)t * QKV_N + HQ*HD + (h - HQ) * HD; nsc = kns; }
    int d = threadIdx.x;
    float v = xr[d];
    float ss = v * v;
    for (int o = 16; o > 0; o >>= 1) ss += __shfl_xor_sync(0xffffffffu, ss, o);
    __shared__ float sw[4];
    if ((d & 31) == 0) sw[d >> 5] = ss;
    __syncthreads();
    float tot = sw[0] + sw[1] + sw[2] + sw[3];
    float xn = v * rsqrtf(tot * (1.f / HD) + 1e-6f) * nsc[d];
    __shared__ float sx[HD];
    sx[d] = xn;
    __syncthreads();
    int dr = d & 63;
    float inv_freq = expf(-(float)dr * 0.21586735246819178f);
    float ang = (float)pos[t] * inv_freq;
    float sn, cs;
    sincosf(ang, &sn, &cs);
    float val = (d < 64) ? (sx[dr] * cs - sx[dr + 64] * sn)
                         : (sx[dr + 64] * cs + sx[dr] * sn);
    bf16 hh, ll;
    split_bf16(val, hh, ll);
    if (isq) {
        size_t o = (size_t)t * (HQ*HD) + h * HD + d;
        qh[o] = hh;
        ql[o] = ll;
    } else {
        size_t o = ((size_t)(h - HQ) * T_TOK + t) * HD + d;
        kh[o] = hh;
        kl[o] = ll;
    }
}

// ===================== V transpose + split: [t][d] -> [kvh][d][t] =====================
__global__ __launch_bounds__(256) void vtrans_split_k(
    const float* __restrict__ qkv, bf16* __restrict__ vth, bf16* __restrict__ vtl) {
    int t0 = blockIdx.x * 32, d0 = blockIdx.y * 32, kvh = blockIdx.z;
    __shared__ float tb[32][33];
    int tx = threadIdx.x & 31, ty = threadIdx.x >> 5;
    const float* src = qkv + HQ*HD + HKV*HD + kvh * HD;
    for (int j = ty; j < 32; j += 8) tb[j][tx] = src[(size_t)(t0 + j) * QKV_N + d0 + tx];
    __syncthreads();
    int px = threadIdx.x & 15, py = threadIdx.x >> 4;
    for (int j = py; j < 32; j += 16) {
        float v0 = tb[2 * px][j], v1 = tb[2 * px + 1][j];
        bf16 h0, l0, h1, l1;
        split_bf16(v0, h0, l0);
        split_bf16(v1, h1, l1);
        size_t o = ((size_t)kvh * HD + d0 + j) * T_TOK + t0 + 2 * px;
        *(uint32_t*)(vth + o) = pack_bf16(h0, h1);
        *(uint32_t*)(vtl + o) = pack_bf16(l0, l1);
    }
}

// ===================== MMA flash attention =====================
// Block: 128 q rows x 1 head, 8 warps (16 rows each). Key tiles of 32,
// double-buffered cp.async. bf16x3 for S=QK^T and O=PV; fp32 online softmax.
// smem: Qhi 40960 | Qlo 40960 | 2 x (Khi 10240|Klo 10240|Vth 10240|Vtl 10240)
#define ATT_SMEM 163840
__global__ __launch_bounds__(256) void fattn_k(
    const bf16* __restrict__ Qhi, const bf16* __restrict__ Qlo,
    const bf16* __restrict__ Khi, const bf16* __restrict__ Klo,
    const bf16* __restrict__ Vthi, const bf16* __restrict__ Vtlo,
    bf16* __restrict__ Ohi, bf16* __restrict__ Olo) {
    int qb = blockIdx.x, h = blockIdx.y;
    int kvh = h >> 3;
    int tid = threadIdx.x, lane = tid & 31, w = tid >> 5;
    int g = lane >> 2, t = lane & 3;
    extern __shared__ char smem[];
    uint32_t sb = smem_u32(smem);
    int qbase = qb * 128;
    const float scale = 0.08838834764831845f;

    // Q tile load (once)
    {
        const bf16* qhp = Qhi + (size_t)qbase * (HQ*HD) + h * HD;
        const bf16* qlp = Qlo + (size_t)qbase * (HQ*HD) + h * HD;
        for (int s = tid; s < 2048; s += 256) {
            int r = s >> 4, j = s & 15;
            uint32_t dst = (uint32_t)((j >> 2) * 10240 + r * 80 + (j & 3) * 16);
            cp16(sb + dst, qhp + (size_t)r * (HQ*HD) + j * 8, 16);
            cp16(sb + 40960 + dst, qlp + (size_t)r * (HQ*HD) + j * 8, 16);
        }
        asm volatile("cp.async.commit_group;");
    }
    int ntiles = qb * 4 + 4;
    const bf16* khp = Khi + (size_t)kvh * T_TOK * HD;
    const bf16* klp = Klo + (size_t)kvh * T_TOK * HD;
    const bf16* vhp = Vthi + (size_t)kvh * HD * T_TOK;
    const bf16* vlp = Vtlo + (size_t)kvh * HD * T_TOK;

    auto issue_kv = [&](int kt, int buf) {
        uint32_t base = sb + 81920 + buf * 40960;
        for (int s = tid; s < 512; s += 256) {
            int r = s >> 4, j = s & 15;
            uint32_t dst = (uint32_t)((j >> 2) * 2560 + r * 80 + (j & 3) * 16);
            cp16(base + dst,         khp + (size_t)(kt * 32 + r) * HD + j * 8, 16);
            cp16(base + 10240 + dst, klp + (size_t)(kt * 32 + r) * HD + j * 8, 16);
        }
        for (int s = tid; s < 512; s += 256) {
            int d = s >> 2, j = s & 3;
            uint32_t dst = (uint32_t)(d * 80 + j * 16);
            cp16(base + 20480 + dst, vhp + (size_t)d * T_TOK + kt * 32 + j * 8, 16);
            cp16(base + 30720 + dst, vlp + (size_t)d * T_TOK + kt * 32 + j * 8, 16);
        }
        asm volatile("cp.async.commit_group;");
    };
    issue_kv(0, 0);
    if (ntiles > 1) issue_kv(1, 1);

    float o[16][4];
#pragma unroll
    for (int i = 0; i < 16; i++)
#pragma unroll
        for (int k = 0; k < 4; k++) o[i][k] = 0.f;
    float m0 = -1e30f, m1 = -1e30f, l0 = 0.f, l1 = 0.f;
    int wr = w * 16;
    int row0 = qbase + wr + g, row1 = row0 + 8;

    for (int kt = 0; kt < ntiles; kt++) {
        if (kt + 1 < ntiles) asm volatile("cp.async.wait_group 1;");
        else                 asm volatile("cp.async.wait_group 0;");
        __syncthreads();
        uint32_t kb = sb + 81920 + (kt & 1) * 40960;
        bool active = (kt * 32 <= qbase + wr + 15);
        if (active) {
            float s[4][4];
#pragma unroll
            for (int nt = 0; nt < 4; nt++)
#pragma unroll
                for (int i = 0; i < 4; i++) s[nt][i] = 0.f;
            // S = Q K^T (bf16 x3)
#pragma unroll
            for (int ks = 0; ks < 8; ks++) {
                uint32_t ra = sb + (ks >> 1) * 10240 + (wr + g) * 80 + (ks & 1) * 32 + t * 4;
                uint32_t Ah[4], Al[4];
                Ah[0] = lds32(ra);
                Ah[1] = lds32(ra + 640);
                Ah[2] = lds32(ra + 16);
                Ah[3] = lds32(ra + 656);
                Al[0] = lds32(ra + 40960);
                Al[1] = lds32(ra + 41600);
                Al[2] = lds32(ra + 40976);
                Al[3] = lds32(ra + 41616);
#pragma unroll
                for (int nt = 0; nt < 4; nt++) {
                    uint32_t rk = kb + (ks >> 1) * 2560 + (nt * 8 + g) * 80 + (ks & 1) * 32 + t * 4;
                    uint32_t bh0 = lds32(rk), bh1 = lds32(rk + 16);
                    uint32_t bl0 = lds32(rk + 10240), bl1 = lds32(rk + 10256);
                    mma_bf16(s[nt], Ah, bh0, bh1);
                    mma_bf16(s[nt], Ah, bl0, bl1);
                    mma_bf16(s[nt], Al, bh0, bh1);
                }
            }
            // scale + causal mask
#pragma unroll
            for (int nt = 0; nt < 4; nt++) {
                int c0 = kt * 32 + nt * 8 + 2 * t;
                s[nt][0] = (c0     <= row0) ? s[nt][0] * scale : -1e30f;
                s[nt][1] = (c0 + 1 <= row0) ? s[nt][1] * scale : -1e30f;
                s[nt][2] = (c0     <= row1) ? s[nt][2] * scale : -1e30f;
                s[nt][3] = (c0 + 1 <= row1) ? s[nt][3] * scale : -1e30f;
            }
            // row maxes (quad reduce)
            float rm0 = -1e30f, rm1 = -1e30f;
#pragma unroll
            for (int nt = 0; nt < 4; nt++) {
                rm0 = fmaxf(rm0, fmaxf(s[nt][0], s[nt][1]));
                rm1 = fmaxf(rm1, fmaxf(s[nt][2], s[nt][3]));
            }
            rm0 = fmaxf(rm0, __shfl_xor_sync(0xffffffffu, rm0, 1));
            rm0 = fmaxf(rm0, __shfl_xor_sync(0xffffffffu, rm0, 2));
            rm1 = fmaxf(rm1, __shfl_xor_sync(0xffffffffu, rm1, 1));
            rm1 = fmaxf(rm1, __shfl_xor_sync(0xffffffffu, rm1, 2));
            float mn0 = fmaxf(m0, rm0), mn1 = fmaxf(m1, rm1);
            float cor0 = __expf(m0 - mn0), cor1 = __expf(m1 - mn1);
            m0 = mn0;
            m1 = mn1;
            float ps0 = 0.f, ps1 = 0.f;
#pragma unroll
            for (int nt = 0; nt < 4; nt++) {
                s[nt][0] = __expf(s[nt][0] - mn0);
                s[nt][1] = __expf(s[nt][1] - mn0);
                s[nt][2] = __expf(s[nt][2] - mn1);
                s[nt][3] = __expf(s[nt][3] - mn1);
                ps0 += s[nt][0] + s[nt][1];
                ps1 += s[nt][2] + s[nt][3];
            }
            ps0 += __shfl_xor_sync(0xffffffffu, ps0, 1);
            ps0 += __shfl_xor_sync(0xffffffffu, ps0, 2);
            ps1 += __shfl_xor_sync(0xffffffffu, ps1, 1);
            ps1 += __shfl_xor_sync(0xffffffffu, ps1, 2);
            l0 = l0 * cor0 + ps0;
            l1 = l1 * cor1 + ps1;
#pragma unroll
            for (int i = 0; i < 16; i++) {
                o[i][0] *= cor0;
                o[i][1] *= cor0;
                o[i][2] *= cor1;
                o[i][3] *= cor1;
            }
            // pack P fragments (A operand of PV): kk selects keys 16kk..16kk+15
            uint32_t Ph[2][4], Pl[2][4];
#pragma unroll
            for (int kk = 0; kk < 2; kk++) {
                int n0t = 2 * kk;
                Ph[kk][0] = pack2f(s[n0t][0], s[n0t][1]);
                Ph[kk][1] = pack2f(s[n0t][2], s[n0t][3]);
                Ph[kk][2] = pack2f(s[n0t + 1][0], s[n0t + 1][1]);
                Ph[kk][3] = pack2f(s[n0t + 1][2], s[n0t + 1][3]);
                Pl[kk][0] = pack2f_lo(s[n0t][0], s[n0t][1], Ph[kk][0]);
                Pl[kk][1] = pack2f_lo(s[n0t][2], s[n0t][3], Ph[kk][1]);
                Pl[kk][2] = pack2f_lo(s[n0t + 1][0], s[n0t + 1][1], Ph[kk][2]);
                Pl[kk][3] = pack2f_lo(s[n0t + 1][2], s[n0t + 1][3], Ph[kk][3]);
            }
            // O += P V (bf16 x3)
#pragma unroll
            for (int kk = 0; kk < 2; kk++) {
#pragma unroll
                for (int nt2 = 0; nt2 < 16; nt2++) {
                    uint32_t rv = kb + 20480 + (nt2 * 8 + g) * 80 + kk * 32 + t * 4;
                    uint32_t bh0 = lds32(rv), bh1 = lds32(rv + 16);
                    uint32_t bl0 = lds32(rv + 10240), bl1 = lds32(rv + 10256);
                    mma_bf16(o[nt2], Ph[kk], bh0, bh1);
                    mma_bf16(o[nt2], Ph[kk], bl0, bl1);
                    mma_bf16(o[nt2], Pl[kk], bh0, bh1);
                }
            }
        }
        __syncthreads();
        if (kt + 2 < ntiles) issue_kv(kt + 2, kt & 1);
    }
    // epilogue: o / l, split, store
    float il0 = 1.f / l0, il1 = 1.f / l1;
#pragma unroll
    for (int nt2 = 0; nt2 < 16; nt2++) {
        int d = nt2 * 8 + 2 * t;
        float v0 = o[nt2][0] * il0, v1 = o[nt2][1] * il0;
        float v2 = o[nt2][2] * il1, v3 = o[nt2][3] * il1;
        size_t b0 = (size_t)row0 * (HQ*HD) + h * HD + d;
        size_t b1 = (size_t)row1 * (HQ*HD) + h * HD + d;
        uint32_t h0 = pack2f(v0, v1), h1p = pack2f(v2, v3);
        *(uint32_t*)(Ohi + b0) = h0;
        *(uint32_t*)(Ohi + b1) = h1p;
        *(uint32_t*)(Olo + b0) = pack2f_lo(v0, v1, h0);
        *(uint32_t*)(Olo + b1) = pack2f_lo(v2, v3, h1p);
    }
}

// ===================== HMMA bf16x3 GEMM (unchanged from R4) =====================
__global__ __launch_bounds__(256) void mma_gemm_k(
    const bf16* __restrict__ Ahi, const bf16* __restrict__ Alo,
    const bf16* __restrict__ Bhi, const bf16* __restrict__ Blo,
    float* __restrict__ C, int ldc,
    int M, int N, int K,
    const int* __restrict__ eoff, const int* __restrict__ agather,
    const int* __restrict__ cscatter, const float* __restrict__ rscale,
    const float* __restrict__ addv) {
    int rb = 0, Me = M;
    const bf16* bh = Bhi;
    const bf16* bl = Blo;
    if (eoff) {
        int e = blockIdx.z;
        rb = eoff[e];
        Me = eoff[e + 1] - rb;
        bh += (size_t)e * N * K;
        bl += (size_t)e * N * K;
    }
    int m0 = blockIdx.y * 128;
    if (m0 >= Me) return;
    int n0 = blockIdx.x * 128;

    extern __shared__ char smem[];
    uint32_t sbase = smem_u32(smem);
    int tid = threadIdx.x;

    int seg0 = tid * 2, seg1 = tid * 2 + 1;
    int r0 = seg0 >> 2, j0 = seg0 & 3;
    int r1 = seg1 >> 2, j1 = seg1 & 3;
    int am0 = m0 + r0, am1 = m0 + r1;
    int av0 = (am0 < Me) ? 16 : 0, av1 = (am1 < Me) ? 16 : 0;
    size_t ar0 = 0, ar1 = 0;
    if (av0) ar0 = (size_t)(agather ? agather[rb + am0] : (rb + am0)) * K;
    if (av1) ar1 = (size_t)(agather ? agather[rb + am1] : (rb + am1)) * K;
    size_t br0 = (size_t)(n0 + r0) * K, br1 = (size_t)(n0 + r1) * K;
    uint32_t dA0 = r0 * 80 + j0 * 16, dA1 = r1 * 80 + j1 * 16;

    auto issue_chunk = [&](int c, int buf) {
        uint32_t sb = sbase + buf * 40960;
        size_t kof = (size_t)c * 32;
        cp16(sb + dA0,         Ahi + ar0 + kof + j0 * 8, av0);
        cp16(sb + dA1,         Ahi + ar1 + kof + j1 * 8, av1);
        cp16(sb + 10240 + dA0, Alo + ar0 + kof + j0 * 8, av0);
        cp16(sb + 10240 + dA1, Alo + ar1 + kof + j1 * 8, av1);
        cp16(sb + 20480 + dA0, bh + br0 + kof + j0 * 8, 16);
        cp16(sb + 20480 + dA1, bh + br1 + kof + j1 * 8, 16);
        cp16(sb + 30720 + dA0, bl + br0 + kof + j0 * 8, 16);
        cp16(sb + 30720 + dA1, bl + br1 + kof + j1 * 8, 16);
        asm volatile("cp.async.commit_group;");
    };

    int lane = tid & 31, warp = tid >> 5;
    int wm = warp >> 1, wn = warp & 1;
    int g = lane >> 2, t = lane & 3;

    float acc[2][8][4];
#pragma unroll
    for (int m = 0; m < 2; m++)
#pragma unroll
        for (int nt = 0; nt < 8; nt++)
#pragma unroll
            for (int i = 0; i < 4; i++) acc[m][nt][i] = 0.f;

    int nch = K / 32;
    issue_chunk(0, 0);
    if (nch > 1) issue_chunk(1, 1);

    for (int c = 0; c < nch; c++) {
        if (c + 1 < nch) asm volatile("cp.async.wait_group 1;");
        else             asm volatile("cp.async.wait_group 0;");
        __syncthreads();
        uint32_t sb = sbase + (c & 1) * 40960;
#pragma unroll
        for (int ks = 0; ks < 2; ks++) {
            uint32_t Ah[2][4], Al[2][4];
#pragma unroll
            for (int m = 0; m < 2; m++) {
                uint32_t ra = sb + (uint32_t)((wm * 32 + m * 16 + g) * 80 + ks * 32 + t * 4);
                Ah[m][0] = lds32(ra);
                Ah[m][1] = lds32(ra + 640);
                Ah[m][2] = lds32(ra + 16);
                Ah[m][3] = lds32(ra + 656);
                Al[m][0] = lds32(ra + 10240);
                Al[m][1] = lds32(ra + 10880);
                Al[m][2] = lds32(ra + 10256);
                Al[m][3] = lds32(ra + 10896);
            }
#pragma unroll
            for (int nt = 0; nt < 8; nt++) {
                uint32_t rbB = sb + 20480 + (uint32_t)((wn * 64 + nt * 8 + g) * 80 + ks * 32 + t * 4);
                uint32_t bh0 = lds32(rbB);
                uint32_t bh1 = lds32(rbB + 16);
                uint32_t bl0 = lds32(rbB + 10240);
                uint32_t bl1 = lds32(rbB + 10256);
#pragma unroll
                for (int m = 0; m < 2; m++) {
                    mma_bf16(acc[m][nt], Ah[m], bh0, bh1);
                    mma_bf16(acc[m][nt], Ah[m], bl0, bl1);
                    mma_bf16(acc[m][nt], Al[m], bh0, bh1);
                }
            }
        }
        __syncthreads();
        if (c + 2 < nch) issue_chunk(c + 2, c & 1);
    }

#pragma unroll
    for (int m = 0; m < 2; m++) {
        int rlow = m0 + wm * 32 + m * 16 + g;
        int rhigh = rlow + 8;
        int crl = 0, crh = 0;
        float scl = 1.f, sch = 1.f;
        bool okl = rlow < Me, okh = rhigh < Me;
        if (okl) {
            crl = cscatter ? cscatter[rb + rlow] : (rb + rlow);
            if (rscale) scl = rscale[rb + rlow];
        }
        if (okh) {
            crh = cscatter ? cscatter[rb + rhigh] : (rb + rhigh);
            if (rscale) sch = rscale[rb + rhigh];
        }
#pragma unroll
        for (int nt = 0; nt < 8; nt++) {
            int col = n0 + wn * 64 + nt * 8 + t * 2;
            float* a = acc[m][nt];
            if (okl) {
                size_t b = (size_t)crl * ldc + col;
                float v0 = a[0] * scl, v1 = a[1] * scl;
                if (addv) { v0 += addv[b]; v1 += addv[b + 1]; }
                C[b] = v0;
                C[b + 1] = v1;
            }
            if (okh) {
                size_t b = (size_t)crh * ldc + col;
                float v2 = a[2] * sch, v3 = a[3] * sch;
                if (addv) { v2 += addv[b]; v3 += addv[b + 1]; }
                C[b] = v2;
                C[b + 1] = v3;
            }
        }
    }
}

// ===================== SIMT sgemm (router only) =====================
__global__ __launch_bounds__(256) void sgemm_k(
    const float* __restrict__ A, const float* __restrict__ B, float* __restrict__ C,
    int M, int N, int K) {
    __shared__ float As[8][128];
    __shared__ float Bs[8][128];
    int m0 = blockIdx.y * 128;
    int n0 = blockIdx.x * 128;
    int tid = threadIdx.x;
    int tx = tid & 15, ty = tid >> 4;
    int a_i = tid >> 1;
    int a_j = (tid & 1) * 4;
    const float* Arow = A + (size_t)(m0 + a_i) * K;
    int b_i = tid >> 5;
    int b_j = (tid & 31) * 4;
    bool bok = (n0 + b_j) < N;
    float acc[8][8];
#pragma unroll
    for (int a = 0; a < 8; a++)
#pragma unroll
        for (int b = 0; b < 8; b++) acc[a][b] = 0.f;
    for (int k0 = 0; k0 < K; k0 += 8) {
        float4 av = *(const float4*)(Arow + k0 + a_j);
        As[a_j + 0][a_i] = av.x;
        As[a_j + 1][a_i] = av.y;
        As[a_j + 2][a_i] = av.z;
        As[a_j + 3][a_i] = av.w;
        float4 bv = make_float4(0.f, 0.f, 0.f, 0.f);
        if (bok) bv = *(const float4*)(B + (size_t)(k0 + b_i) * N + n0 + b_j);
        *(float4*)&Bs[b_i][b_j] = bv;
        __syncthreads();
#pragma unroll
        for (int j = 0; j < 8; ++j) {
            float ra[8], rbv[8];
#pragma unroll
            for (int a = 0; a < 8; a++) ra[a] = As[j][ty * 8 + a];
#pragma unroll
            for (int b = 0; b < 8; b++) rbv[b] = Bs[j][tx * 8 + b];
#pragma unroll
            for (int a = 0; a < 8; a++)
#pragma unroll
                for (int b = 0; b < 8; b++) acc[a][b] += ra[a] * rbv[b];
        }
        __syncthreads();
    }
#pragma unroll
    for (int a = 0; a < 8; a++) {
        int r = m0 + ty * 8 + a;
        float* Crow = C + (size_t)r * N;
#pragma unroll
        for (int b = 0; b < 8; b++) {
            int ccol = n0 + tx * 8 + b;
            if (ccol < N) Crow[ccol] = acc[a][b];
        }
    }
}

// ===================== router top-8 =====================
__global__ __launch_bounds__(256) void topk_k(const float* __restrict__ logits,
                                              int* __restrict__ idx,
                                              float* __restrict__ wts) {
    int t = blockIdx.x * 8 + (threadIdx.x >> 5);
    int lane = threadIdx.x & 31;
    if (t >= T_TOK) return;
    const float* lr = logits + (size_t)t * NE;
    float v0 = lr[lane], v1 = lr[lane + 32];
    float selv[TOPK];
    int seli[TOPK];
    for (int s = 0; s < TOPK; s++) {
        float bv = v0;
        int bi = lane;
        if (v1 > bv) { bv = v1; bi = lane + 32; }
        for (int off = 16; off > 0; off >>= 1) {
            float ov = __shfl_xor_sync(0xffffffffu, bv, off);
            int oi = __shfl_xor_sync(0xffffffffu, bi, off);
            if (ov > bv || (ov == bv && oi < bi)) { bv = ov; bi = oi; }
        }
        selv[s] = bv;
        seli[s] = bi;
        if (bi == lane) v0 = -1e30f;
        if (bi == lane + 32) v1 = -1e30f;
    }
    if (lane == 0) {
        float mx = selv[0];
        float e[TOPK], sum = 0.f;
        for (int s = 0; s < TOPK; s++) { e[s] = __expf(selv[s] - mx); sum += e[s]; }
        float inv = 1.f / sum;
        for (int s = 0; s < TOPK; s++) {
            idx[t * TOPK + s] = seli[s];
            wts[t * TOPK + s] = e[s] * inv;
        }
    }
}

// ===================== routing plumbing =====================
__global__ void zero64_k(int* c) { if (threadIdx.x < NE) c[threadIdx.x] = 0; }

__global__ void count_k(const int* __restrict__ idx, int* __restrict__ counts) {
    int i = blockIdx.x * blockDim.x + threadIdx.x;
    if (i < T_TOK * TOPK) atomicAdd(&counts[idx[i]], 1);
}

__global__ void scan_k(const int* __restrict__ counts, int* __restrict__ off,
                       int* __restrict__ cursor) {
    if (threadIdx.x == 0) {
        int s = 0;
        for (int e = 0; e < NE; e++) { off[e] = s; cursor[e] = s; s += counts[e]; }
        off[NE] = s;
    }
}

__global__ void fill_k(const int* __restrict__ idx, const float* __restrict__ wts,
                       int* __restrict__ cursor, int* __restrict__ tok,
                       int* __restrict__ crow, float* __restrict__ rsc) {
    int i = blockIdx.x * blockDim.x + threadIdx.x;
    if (i < T_TOK * TOPK) {
        int t = i >> 3;
        int e = idx[i];
        int p = atomicAdd(&cursor[e], 1);
        tok[p] = t;
        crow[p] = i;
        rsc[p] = wts[i];
    }
}

// ===================== silu(g)*u -> split bf16 act =====================
__global__ void silumul_split_k(const float* __restrict__ gu,
                                bf16* __restrict__ ahi, bf16* __restrict__ alo) {
    int i = blockIdx.x * blockDim.x + threadIdx.x;
    if (i < NROWS * FF) {
        int r = i / FF, j = i - r * FF;
        float g = gu[(size_t)r * GU_N + j];
        float u = gu[(size_t)r * GU_N + FF + j];
        float a = (g / (1.f + __expf(-g))) * u;
        bf16 h, l;
        split_bf16(a, h, l);
        ahi[i] = h;
        alo[i] = l;
    }
}

// ===================== combine 8 slots =====================
__global__ void combine_k(const float* __restrict__ part, float* __restrict__ out) {
    int i = blockIdx.x * blockDim.x + threadIdx.x;
    if (i < T_TOK * D_DIM) {
        int t = i >> 11;
        int d = i & 2047;
        float s = 0.f;
#pragma unroll
        for (int sl = 0; sl < TOPK; sl++)
            s += part[((size_t)(t * TOPK + sl)) * D_DIM + d];
        out[i] = s;
    }
}

// ===================== launch =====================
#define MMA_SMEM 81920

extern "C" void kernel_launch(void* const* d_in, const int* in_sizes, int n_in,
                              void* d_out, int out_size) {
    const int*   positions = (const int*)d_in[0];
    const float* hidden    = (const float*)d_in[1];
    const float* in_ln     = (const float*)d_in[2];
    const float* post_ln   = (const float*)d_in[3];
    const float* qns       = (const float*)d_in[4];
    const float* kns       = (const float*)d_in[5];
    const float* wq        = (const float*)d_in[6];
    const float* wk        = (const float*)d_in[7];
    const float* wv        = (const float*)d_in[8];
    const float* wo        = (const float*)d_in[9];
    const float* wr        = (const float*)d_in[10];
    const float* wg        = (const float*)d_in[11];
    const float* wu        = (const float*)d_in[12];
    const float* wd        = (const float*)d_in[13];

    float* outp   = (float*)d_out;
    float* residp = outp + (size_t)T_TOK * D_DIM;

    cudaFuncSetAttribute(mma_gemm_k, cudaFuncAttributeMaxDynamicSharedMemorySize, MMA_SMEM);
    cudaFuncSetAttribute(fattn_k, cudaFuncAttributeMaxDynamicSharedMemorySize, ATT_SMEM);

    bf16 *qkvT_hi, *qkvT_lo, *woT_hi, *woT_lo, *wguT_hi, *wguT_lo, *wdT_hi, *wdT_lo;
    bf16 *hn_hi, *hn_lo, *qh, *ql, *kh, *kl, *vth, *vtl;
    bf16 *ao_hi, *ao_lo, *h2n_hi, *h2n_lo, *act_hi, *act_lo;
    float *qkv, *h2n, *logits, *twt, *rsc, *gu, *part;
    int *tidx, *counts, *off, *cursor, *tok, *crow;
    cudaGetSymbolAddress((void**)&qkvT_hi, g_qkvT_hi);
    cudaGetSymbolAddress((void**)&qkvT_lo, g_qkvT_lo);
    cudaGetSymbolAddress((void**)&woT_hi, g_woT_hi);
    cudaGetSymbolAddress((void**)&woT_lo, g_woT_lo);
    cudaGetSymbolAddress((void**)&wguT_hi, g_wguT_hi);
    cudaGetSymbolAddress((void**)&wguT_lo, g_wguT_lo);
    cudaGetSymbolAddress((void**)&wdT_hi, g_wdT_hi);
    cudaGetSymbolAddress((void**)&wdT_lo, g_wdT_lo);
    cudaGetSymbolAddress((void**)&hn_hi, g_hn_hi);
    cudaGetSymbolAddress((void**)&hn_lo, g_hn_lo);
    cudaGetSymbolAddress((void**)&qkv, g_qkv);
    cudaGetSymbolAddress((void**)&qh, g_qh);
    cudaGetSymbolAddress((void**)&ql, g_ql);
    cudaGetSymbolAddress((void**)&kh, g_kh);
    cudaGetSymbolAddress((void**)&kl, g_kl);
    cudaGetSymbolAddress((void**)&vth, g_vth);
    cudaGetSymbolAddress((void**)&vtl, g_vtl);
    cudaGetSymbolAddress((void**)&ao_hi, g_ao_hi);
    cudaGetSymbolAddress((void**)&ao_lo, g_ao_lo);
    cudaGetSymbolAddress((void**)&h2n, g_h2n);
    cudaGetSymbolAddress((void**)&h2n_hi, g_h2n_hi);
    cudaGetSymbolAddress((void**)&h2n_lo, g_h2n_lo);
    cudaGetSymbolAddress((void**)&logits, g_logits);
    cudaGetSymbolAddress((void**)&tidx, g_tidx);
    cudaGetSymbolAddress((void**)&twt, g_twt);
    cudaGetSymbolAddress((void**)&counts, g_counts);
    cudaGetSymbolAddress((void**)&off, g_off);
    cudaGetSymbolAddress((void**)&cursor, g_cursor);
    cudaGetSymbolAddress((void**)&tok, g_tok);
    cudaGetSymbolAddress((void**)&crow, g_crow);
    cudaGetSymbolAddress((void**)&rsc, g_rsc);
    cudaGetSymbolAddress((void**)&gu, g_gu);
    cudaGetSymbolAddress((void**)&act_hi, g_act_hi);
    cudaGetSymbolAddress((void**)&act_lo, g_act_lo);
    cudaGetSymbolAddress((void**)&part, g_part);

    // 0. weight transposes + bf16 splits (B^T layouts)
    transpose_split_k<<<dim3(HQ*HD/32, D_DIM/32, 1), 256>>>(wq, qkvT_hi, qkvT_lo,
        D_DIM, HQ*HD, D_DIM, 0, 0, 0);
    transpose_split_k<<<dim3(HKV*HD/32, D_DIM/32, 1), 256>>>(wk, qkvT_hi, qkvT_lo,
        D_DIM, HKV*HD, D_DIM, HQ*HD, 0, 0);
    transpose_split_k<<<dim3(HKV*HD/32, D_DIM/32, 1), 256>>>(wv, qkvT_hi, qkvT_lo,
        D_DIM, HKV*HD, D_DIM, HQ*HD + HKV*HD, 0, 0);
    transpose_split_k<<<dim3(D_DIM/32, (HQ*HD)/32, 1), 256>>>(wo, woT_hi, woT_lo,
        HQ*HD, D_DIM, HQ*HD, 0, 0, 0);
    transpose_split_k<<<dim3(FF/32, D_DIM/32, NE), 256>>>(wg, wguT_hi, wguT_lo,
        D_DIM, FF, D_DIM, 0, (size_t)D_DIM*FF, (size_t)GU_N*D_DIM);
    transpose_split_k<<<dim3(FF/32, D_DIM/32, NE), 256>>>(wu, wguT_hi, wguT_lo,
        D_DIM, FF, D_DIM, FF, (size_t)D_DIM*FF, (size_t)GU_N*D_DIM);
    transpose_split_k<<<dim3(D_DIM/32, FF/32, NE), 256>>>(wd, wdT_hi, wdT_lo,
        FF, D_DIM, FF, 0, (size_t)FF*D_DIM, (size_t)D_DIM*FF);

    // 1. pre-attention rmsnorm (split only)
    rmsnorm_split_k<<<T_TOK, 256>>>(hidden, in_ln, nullptr, hn_hi, hn_lo);

    // 2. fused QKV projection (fp32 out)
    mma_gemm_k<<<dim3(QKV_N/128, T_TOK/128, 1), 256, MMA_SMEM>>>(
        hn_hi, hn_lo, qkvT_hi, qkvT_lo, qkv, QKV_N, T_TOK, QKV_N, D_DIM,
        nullptr, nullptr, nullptr, nullptr, nullptr);

    // 3. QK rmsnorm + rope -> split bf16; V transpose + split
    qknorm_rope_split_k<<<dim3(T_TOK, HQ + HKV), 128>>>(qkv, qns, kns, positions,
                                                        qh, ql, kh, kl);
    vtrans_split_k<<<dim3(T_TOK/32, HD/32, HKV), 256>>>(qkv, vth, vtl);

    // 4. MMA flash attention
    fattn_k<<<dim3(T_TOK/128, HQ), 256, ATT_SMEM>>>(qh, ql, kh, kl, vth, vtl,
                                                    ao_hi, ao_lo);

    // 5. O projection + residual
    mma_gemm_k<<<dim3(D_DIM/128, T_TOK/128, 1), 256, MMA_SMEM>>>(
        ao_hi, ao_lo, woT_hi, woT_lo, residp, D_DIM, T_TOK, D_DIM, HQ*HD,
        nullptr, nullptr, nullptr, nullptr, hidden);

    // 6. post-attention rmsnorm
    rmsnorm_split_k<<<T_TOK, 256>>>(residp, post_ln, h2n, h2n_hi, h2n_lo);

    // 7. router + top-8
    sgemm_k<<<dim3(1, T_TOK/128, 1), 256>>>(h2n, wr, logits, T_TOK, NE, D_DIM);
    topk_k<<<T_TOK / 8, 256>>>(logits, tidx, twt);

    // 8. per-expert token lists
    zero64_k<<<1, 64>>>(counts);
    count_k<<<(T_TOK * TOPK + 255) / 256, 256>>>(tidx, counts);
    scan_k<<<1, 32>>>(counts, off, cursor);
    fill_k<<<(T_TOK * TOPK + 255) / 256, 256>>>(tidx, twt, cursor, tok, crow, rsc);

    // 9. fused gate+up gather-GEMM per expert
    mma_gemm_k<<<dim3(GU_N/128, 16, NE), 256, MMA_SMEM>>>(
        h2n_hi, h2n_lo, wguT_hi, wguT_lo, gu, GU_N, T_TOK, GU_N, D_DIM,
        off, tok, nullptr, nullptr, nullptr);

    // 10. silu(g)*u split
    silumul_split_k<<<(NROWS * FF + 255) / 256, 256>>>(gu, act_hi, act_lo);

    // 11. down scatter-GEMM per expert
    mma_gemm_k<<<dim3(D_DIM/128, 16, NE), 256, MMA_SMEM>>>(
        act_hi, act_lo, wdT_hi, wdT_lo, part, D_DIM, T_TOK, D_DIM, FF,
        off, nullptr, crow, rsc, nullptr);

    // 12. combine
    combine_k<<<(T_TOK * D_DIM + 255) / 256, 256>>>(part, outp);
}

// round 6
// speedup vs baseline: 3.0169x; 1.1210x over previous
#include <cuda_runtime.h>
#include <cuda_bf16.h>
#include <math.h>
#include <stdint.h>

// Problem constants
#define T_TOK 2048
#define D_DIM 2048
#define HQ 32
#define HKV 4
#define HD 128
#define NE 64
#define TOPK 8
#define FF 768
#define NROWS (T_TOK*TOPK)
#define QKV_N (HQ*HD + 2*HKV*HD)   // 5120
#define GU_N  (2*FF)               // 1536

typedef __nv_bfloat16 bf16;

__device__ __forceinline__ uint32_t smem_u32(const void* p) {
    uint32_t a;
    asm("{ .reg .u64 t; cvta.to.shared.u64 t, %1; cvt.u32.u64 %0, t; }" : "=r"(a) : "l"(p));
    return a;
}
__device__ __forceinline__ uint32_t lds32(uint32_t addr) {
    uint32_t v;
    asm volatile("ld.shared.b32 %0, [%1];" : "=r"(v) : "r"(addr));
    return v;
}
__device__ __forceinline__ float ldsf(uint32_t addr) {
    float v;
    asm volatile("ld.shared.f32 %0, [%1];" : "=f"(v) : "r"(addr));
    return v;
}
__device__ __forceinline__ void cp16(uint32_t dst, const void* src, int sz) {
    asm volatile("cp.async.cg.shared.global [%0], [%1], 16, %2;"
                 :: "r"(dst), "l"(src), "r"(sz));
}
__device__ __forceinline__ void mma_bf16(float* d, const uint32_t* a, uint32_t b0, uint32_t b1) {
    asm volatile("mma.sync.aligned.m16n8k16.row.col.f32.bf16.bf16.f32 "
                 "{%0,%1,%2,%3}, {%4,%5,%6,%7}, {%8,%9}, {%0,%1,%2,%3};"
                 : "+f"(d[0]), "+f"(d[1]), "+f"(d[2]), "+f"(d[3])
                 : "r"(a[0]), "r"(a[1]), "r"(a[2]), "r"(a[3]), "r"(b0), "r"(b1));
}
__device__ __forceinline__ void split_bf16(float x, bf16& h, bf16& l) {
    h = __float2bfloat16(x);
    l = __float2bfloat16(x - __bfloat162float(h));
}
__device__ __forceinline__ uint32_t pack_bf16(bf16 a, bf16 b) {
    return (uint32_t)__bfloat16_as_ushort(a) | ((uint32_t)__bfloat16_as_ushort(b) << 16);
}
__device__ __forceinline__ uint32_t pack2f(float a, float b) {
    return pack_bf16(__float2bfloat16(a), __float2bfloat16(b));
}
__device__ __forceinline__ uint32_t pack2f_lo(float a, float b, uint32_t hipair) {
    float ha = __bfloat162float(__ushort_as_bfloat16((unsigned short)(hipair & 0xFFFF)));
    float hb = __bfloat162float(__ushort_as_bfloat16((unsigned short)(hipair >> 16)));
    return pack_bf16(__float2bfloat16(a - ha), __float2bfloat16(b - hb));
}
// split two floats -> packed hi pair (lo16=f0) and packed lo pair
__device__ __forceinline__ void splitpack2(float f0, float f1, uint32_t& h, uint32_t& l) {
    float h0 = __bfloat162float(__float2bfloat16(f0));
    float h1 = __bfloat162float(__float2bfloat16(f1));
    asm("cvt.rn.bf16x2.f32 %0, %1, %2;" : "=r"(h) : "f"(f1), "f"(f0));
    float l0 = f0 - h0, l1 = f1 - h1;
    asm("cvt.rn.bf16x2.f32 %0, %1, %2;" : "=r"(l) : "f"(l1), "f"(l0));
}

// ===================== scratch =====================
__device__ bf16 g_hn_hi[(size_t)T_TOK * D_DIM];
__device__ bf16 g_hn_lo[(size_t)T_TOK * D_DIM];
__device__ float g_qkv[(size_t)T_TOK * QKV_N];
__device__ bf16 g_qh[(size_t)T_TOK * HQ*HD];
__device__ bf16 g_ql[(size_t)T_TOK * HQ*HD];
__device__ bf16 g_kh[(size_t)HKV * T_TOK * HD];
__device__ bf16 g_kl[(size_t)HKV * T_TOK * HD];
__device__ bf16 g_vth[(size_t)HKV * HD * T_TOK];
__device__ bf16 g_vtl[(size_t)HKV * HD * T_TOK];
__device__ bf16 g_ao_hi[(size_t)T_TOK * (HQ*HD)];
__device__ bf16 g_ao_lo[(size_t)T_TOK * (HQ*HD)];
__device__ float g_h2n[(size_t)T_TOK * D_DIM];
__device__ bf16 g_h2n_hi[(size_t)T_TOK * D_DIM];
__device__ bf16 g_h2n_lo[(size_t)T_TOK * D_DIM];
__device__ float g_logits[T_TOK*NE];
__device__ int   g_tidx[T_TOK*TOPK];
__device__ float g_twt[T_TOK*TOPK];
__device__ int   g_counts[NE];
__device__ int   g_off[NE+1];
__device__ int   g_cursor[NE];
__device__ int   g_tok[NROWS];
__device__ int   g_crow[NROWS];
__device__ float g_rsc[NROWS];
__device__ float g_gu[(size_t)NROWS * GU_N];
__device__ bf16 g_act_hi[(size_t)NROWS * FF];
__device__ bf16 g_act_lo[(size_t)NROWS * FF];
__device__ float g_part[(size_t)NROWS * D_DIM];

// ===================== rmsnorm (+ optional fp32 full, + bf16 split) =====================
__global__ __launch_bounds__(256) void rmsnorm_split_k(
    const float* __restrict__ x, const float* __restrict__ sc,
    float* __restrict__ full, bf16* __restrict__ hi, bf16* __restrict__ lo) {
    int row = blockIdx.x;
    const float* xr = x + (size_t)row * D_DIM;
    float ss = 0.f;
    for (int i = threadIdx.x; i < D_DIM; i += 256) { float v = xr[i]; ss += v * v; }
    for (int o = 16; o > 0; o >>= 1) ss += __shfl_xor_sync(0xffffffffu, ss, o);
    __shared__ float sw[8];
    if ((threadIdx.x & 31) == 0) sw[threadIdx.x >> 5] = ss;
    __syncthreads();
    float tot = 0.f;
#pragma unroll
    for (int i = 0; i < 8; i++) tot += sw[i];
    float inv = rsqrtf(tot * (1.f / D_DIM) + 1e-6f);
    size_t base = (size_t)row * D_DIM;
    for (int i = threadIdx.x; i < D_DIM; i += 256) {
        float v = xr[i] * inv * sc[i];
        if (full) full[base + i] = v;
        bf16 h, l;
        split_bf16(v, h, l);
        hi[base + i] = h;
        lo[base + i] = l;
    }
}

// ===================== qk norm + rope -> split bf16 =====================
__global__ __launch_bounds__(128) void qknorm_rope_split_k(
    const float* __restrict__ qkv,
    const float* __restrict__ qns, const float* __restrict__ kns,
    const int* __restrict__ pos,
    bf16* __restrict__ qh, bf16* __restrict__ ql,
    bf16* __restrict__ kh, bf16* __restrict__ kl) {
    int t = blockIdx.x, h = blockIdx.y;  // 0..31 q, 32..35 k
    bool isq = h < HQ;
    const float* xr;
    const float* nsc;
    if (isq) { xr = qkv + (size_t)t * QKV_N + h * HD; nsc = qns; }
    else     { xr = qkv + (size_t)t * QKV_N + HQ*HD + (h - HQ) * HD; nsc = kns; }
    int d = threadIdx.x;
    float v = xr[d];
    float ss = v * v;
    for (int o = 16; o > 0; o >>= 1) ss += __shfl_xor_sync(0xffffffffu, ss, o);
    __shared__ float sw[4];
    if ((d & 31) == 0) sw[d >> 5] = ss;
    __syncthreads();
    float tot = sw[0] + sw[1] + sw[2] + sw[3];
    float xn = v * rsqrtf(tot * (1.f / HD) + 1e-6f) * nsc[d];
    __shared__ float sx[HD];
    sx[d] = xn;
    __syncthreads();
    int dr = d & 63;
    float inv_freq = expf(-(float)dr * 0.21586735246819178f);
    float ang = (float)pos[t] * inv_freq;
    float sn, cs;
    sincosf(ang, &sn, &cs);
    float val = (d < 64) ? (sx[dr] * cs - sx[dr + 64] * sn)
                         : (sx[dr + 64] * cs + sx[dr] * sn);
    bf16 hh, ll;
    split_bf16(val, hh, ll);
    if (isq) {
        size_t o = (size_t)t * (HQ*HD) + h * HD + d;
        qh[o] = hh;
        ql[o] = ll;
    } else {
        size_t o = ((size_t)(h - HQ) * T_TOK + t) * HD + d;
        kh[o] = hh;
        kl[o] = ll;
    }
}

// ===================== V transpose + split: [t][d] -> [kvh][d][t] =====================
__global__ __launch_bounds__(256) void vtrans_split_k(
    const float* __restrict__ qkv, bf16* __restrict__ vth, bf16* __restrict__ vtl) {
    int t0 = blockIdx.x * 32, d0 = blockIdx.y * 32, kvh = blockIdx.z;
    __shared__ float tb[32][33];
    int tx = threadIdx.x & 31, ty = threadIdx.x >> 5;
    const float* src = qkv + HQ*HD + HKV*HD + kvh * HD;
    for (int j = ty; j < 32; j += 8) tb[j][tx] = src[(size_t)(t0 + j) * QKV_N + d0 + tx];
    __syncthreads();
    int px = threadIdx.x & 15, py = threadIdx.x >> 4;
    for (int j = py; j < 32; j += 16) {
        float v0 = tb[2 * px][j], v1 = tb[2 * px + 1][j];
        bf16 h0, l0, h1, l1;
        split_bf16(v0, h0, l0);
        split_bf16(v1, h1, l1);
        size_t o = ((size_t)kvh * HD + d0 + j) * T_TOK + t0 + 2 * px;
        *(uint32_t*)(vth + o) = pack_bf16(h0, h1);
        *(uint32_t*)(vtl + o) = pack_bf16(l0, l1);
    }
}

// ===================== MMA flash attention (unchanged from R5) =====================
#define ATT_SMEM 163840
__global__ __launch_bounds__(256) void fattn_k(
    const bf16* __restrict__ Qhi, const bf16* __restrict__ Qlo,
    const bf16* __restrict__ Khi, const bf16* __restrict__ Klo,
    const bf16* __restrict__ Vthi, const bf16* __restrict__ Vtlo,
    bf16* __restrict__ Ohi, bf16* __restrict__ Olo) {
    int qb = blockIdx.x, h = blockIdx.y;
    int kvh = h >> 3;
    int tid = threadIdx.x, lane = tid & 31, w = tid >> 5;
    int g = lane >> 2, t = lane & 3;
    extern __shared__ char smem[];
    uint32_t sb = smem_u32(smem);
    int qbase = qb * 128;
    const float scale = 0.08838834764831845f;

    {
        const bf16* qhp = Qhi + (size_t)qbase * (HQ*HD) + h * HD;
        const bf16* qlp = Qlo + (size_t)qbase * (HQ*HD) + h * HD;
        for (int s = tid; s < 2048; s += 256) {
            int r = s >> 4, j = s & 15;
            uint32_t dst = (uint32_t)((j >> 2) * 10240 + r * 80 + (j & 3) * 16);
            cp16(sb + dst, qhp + (size_t)r * (HQ*HD) + j * 8, 16);
            cp16(sb + 40960 + dst, qlp + (size_t)r * (HQ*HD) + j * 8, 16);
        }
        asm volatile("cp.async.commit_group;");
    }
    int ntiles = qb * 4 + 4;
    const bf16* khp = Khi + (size_t)kvh * T_TOK * HD;
    const bf16* klp = Klo + (size_t)kvh * T_TOK * HD;
    const bf16* vhp = Vthi + (size_t)kvh * HD * T_TOK;
    const bf16* vlp = Vtlo + (size_t)kvh * HD * T_TOK;

    auto issue_kv = [&](int kt, int buf) {
        uint32_t base = sb + 81920 + buf * 40960;
        for (int s = tid; s < 512; s += 256) {
            int r = s >> 4, j = s & 15;
            uint32_t dst = (uint32_t)((j >> 2) * 2560 + r * 80 + (j & 3) * 16);
            cp16(base + dst,         khp + (size_t)(kt * 32 + r) * HD + j * 8, 16);
            cp16(base + 10240 + dst, klp + (size_t)(kt * 32 + r) * HD + j * 8, 16);
        }
        for (int s = tid; s < 512; s += 256) {
            int d = s >> 2, j = s & 3;
            uint32_t dst = (uint32_t)(d * 80 + j * 16);
            cp16(base + 20480 + dst, vhp + (size_t)d * T_TOK + kt * 32 + j * 8, 16);
            cp16(base + 30720 + dst, vlp + (size_t)d * T_TOK + kt * 32 + j * 8, 16);
        }
        asm volatile("cp.async.commit_group;");
    };
    issue_kv(0, 0);
    if (ntiles > 1) issue_kv(1, 1);

    float o[16][4];
#pragma unroll
    for (int i = 0; i < 16; i++)
#pragma unroll
        for (int k = 0; k < 4; k++) o[i][k] = 0.f;
    float m0 = -1e30f, m1 = -1e30f, l0 = 0.f, l1 = 0.f;
    int wr = w * 16;
    int row0 = qbase + wr + g, row1 = row0 + 8;

    for (int kt = 0; kt < ntiles; kt++) {
        if (kt + 1 < ntiles) asm volatile("cp.async.wait_group 1;");
        else                 asm volatile("cp.async.wait_group 0;");
        __syncthreads();
        uint32_t kb = sb + 81920 + (kt & 1) * 40960;
        bool active = (kt * 32 <= qbase + wr + 15);
        if (active) {
            float s[4][4];
#pragma unroll
            for (int nt = 0; nt < 4; nt++)
#pragma unroll
                for (int i = 0; i < 4; i++) s[nt][i] = 0.f;
#pragma unroll
            for (int ks = 0; ks < 8; ks++) {
                uint32_t ra = sb + (ks >> 1) * 10240 + (wr + g) * 80 + (ks & 1) * 32 + t * 4;
                uint32_t Ah[4], Al[4];
                Ah[0] = lds32(ra);
                Ah[1] = lds32(ra + 640);
                Ah[2] = lds32(ra + 16);
                Ah[3] = lds32(ra + 656);
                Al[0] = lds32(ra + 40960);
                Al[1] = lds32(ra + 41600);
                Al[2] = lds32(ra + 40976);
                Al[3] = lds32(ra + 41616);
#pragma unroll
                for (int nt = 0; nt < 4; nt++) {
                    uint32_t rk = kb + (ks >> 1) * 2560 + (nt * 8 + g) * 80 + (ks & 1) * 32 + t * 4;
                    uint32_t bh0 = lds32(rk), bh1 = lds32(rk + 16);
                    uint32_t bl0 = lds32(rk + 10240), bl1 = lds32(rk + 10256);
                    mma_bf16(s[nt], Ah, bh0, bh1);
                    mma_bf16(s[nt], Ah, bl0, bl1);
                    mma_bf16(s[nt], Al, bh0, bh1);
                }
            }
#pragma unroll
            for (int nt = 0; nt < 4; nt++) {
                int c0 = kt * 32 + nt * 8 + 2 * t;
                s[nt][0] = (c0     <= row0) ? s[nt][0] * scale : -1e30f;
                s[nt][1] = (c0 + 1 <= row0) ? s[nt][1] * scale : -1e30f;
                s[nt][2] = (c0     <= row1) ? s[nt][2] * scale : -1e30f;
                s[nt][3] = (c0 + 1 <= row1) ? s[nt][3] * scale : -1e30f;
            }
            float rm0 = -1e30f, rm1 = -1e30f;
#pragma unroll
            for (int nt = 0; nt < 4; nt++) {
                rm0 = fmaxf(rm0, fmaxf(s[nt][0], s[nt][1]));
                rm1 = fmaxf(rm1, fmaxf(s[nt][2], s[nt][3]));
            }
            rm0 = fmaxf(rm0, __shfl_xor_sync(0xffffffffu, rm0, 1));
            rm0 = fmaxf(rm0, __shfl_xor_sync(0xffffffffu, rm0, 2));
            rm1 = fmaxf(rm1, __shfl_xor_sync(0xffffffffu, rm1, 1));
            rm1 = fmaxf(rm1, __shfl_xor_sync(0xffffffffu, rm1, 2));
            float mn0 = fmaxf(m0, rm0), mn1 = fmaxf(m1, rm1);
            float cor0 = __expf(m0 - mn0), cor1 = __expf(m1 - mn1);
            m0 = mn0;
            m1 = mn1;
            float ps0 = 0.f, ps1 = 0.f;
#pragma unroll
            for (int nt = 0; nt < 4; nt++) {
                s[nt][0] = __expf(s[nt][0] - mn0);
                s[nt][1] = __expf(s[nt][1] - mn0);
                s[nt][2] = __expf(s[nt][2] - mn1);
                s[nt][3] = __expf(s[nt][3] - mn1);
                ps0 += s[nt][0] + s[nt][1];
                ps1 += s[nt][2] + s[nt][3];
            }
            ps0 += __shfl_xor_sync(0xffffffffu, ps0, 1);
            ps0 += __shfl_xor_sync(0xffffffffu, ps0, 2);
            ps1 += __shfl_xor_sync(0xffffffffu, ps1, 1);
            ps1 += __shfl_xor_sync(0xffffffffu, ps1, 2);
            l0 = l0 * cor0 + ps0;
            l1 = l1 * cor1 + ps1;
#pragma unroll
            for (int i = 0; i < 16; i++) {
                o[i][0] *= cor0;
                o[i][1] *= cor0;
                o[i][2] *= cor1;
                o[i][3] *= cor1;
            }
            uint32_t Ph[2][4], Pl[2][4];
#pragma unroll
            for (int kk = 0; kk < 2; kk++) {
                int n0t = 2 * kk;
                Ph[kk][0] = pack2f(s[n0t][0], s[n0t][1]);
                Ph[kk][1] = pack2f(s[n0t][2], s[n0t][3]);
                Ph[kk][2] = pack2f(s[n0t + 1][0], s[n0t + 1][1]);
                Ph[kk][3] = pack2f(s[n0t + 1][2], s[n0t + 1][3]);
                Pl[kk][0] = pack2f_lo(s[n0t][0], s[n0t][1], Ph[kk][0]);
                Pl[kk][1] = pack2f_lo(s[n0t][2], s[n0t][3], Ph[kk][1]);
                Pl[kk][2] = pack2f_lo(s[n0t + 1][0], s[n0t + 1][1], Ph[kk][2]);
                Pl[kk][3] = pack2f_lo(s[n0t + 1][2], s[n0t + 1][3], Ph[kk][3]);
            }
#pragma unroll
            for (int kk = 0; kk < 2; kk++) {
#pragma unroll
                for (int nt2 = 0; nt2 < 16; nt2++) {
                    uint32_t rv = kb + 20480 + (nt2 * 8 + g) * 80 + kk * 32 + t * 4;
                    uint32_t bh0 = lds32(rv), bh1 = lds32(rv + 16);
                    uint32_t bl0 = lds32(rv + 10240), bl1 = lds32(rv + 10256);
                    mma_bf16(o[nt2], Ph[kk], bh0, bh1);
                    mma_bf16(o[nt2], Ph[kk], bl0, bl1);
                    mma_bf16(o[nt2], Pl[kk], bh0, bh1);
                }
            }
        }
        __syncthreads();
        if (kt + 2 < ntiles) issue_kv(kt + 2, kt & 1);
    }
    float il0 = 1.f / l0, il1 = 1.f / l1;
#pragma unroll
    for (int nt2 = 0; nt2 < 16; nt2++) {
        int d = nt2 * 8 + 2 * t;
        float v0 = o[nt2][0] * il0, v1 = o[nt2][1] * il0;
        float v2 = o[nt2][2] * il1, v3 = o[nt2][3] * il1;
        size_t b0 = (size_t)row0 * (HQ*HD) + h * HD + d;
        size_t b1 = (size_t)row1 * (HQ*HD) + h * HD + d;
        uint32_t h0 = pack2f(v0, v1), h1p = pack2f(v2, v3);
        *(uint32_t*)(Ohi + b0) = h0;
        *(uint32_t*)(Ohi + b1) = h1p;
        *(uint32_t*)(Olo + b0) = pack2f_lo(v0, v1, h0);
        *(uint32_t*)(Olo + b1) = pack2f_lo(v2, v3, h1p);
    }
}

// ===================== HMMA bf16x3 GEMM, B = raw fp32 [K][N] natural layout =====================
// A pre-split bf16 hi/lo [M][K]. B fp32 split to hi/lo on the fly in fragment load.
// smem/buffer: Ahi @0 (10240), Alo @10240, Bf32 @20480 (32 rows x 528B = 16896).
// buffer stride 40960, double buffered.
__global__ __launch_bounds__(256) void mma_gemm_k(
    const bf16* __restrict__ Ahi, const bf16* __restrict__ Alo,
    const float* __restrict__ B, size_t bStrideE,
    float* __restrict__ C, int ldc,
    int M, int N, int K,
    const int* __restrict__ eoff, const int* __restrict__ agather,
    const int* __restrict__ cscatter, const float* __restrict__ rscale,
    const float* __restrict__ addv) {
    int rb = 0, Me = M;
    const float* Bp = B;
    if (eoff) {
        int e = blockIdx.z;
        rb = eoff[e];
        Me = eoff[e + 1] - rb;
        Bp += (size_t)e * bStrideE;
    }
    int m0 = blockIdx.y * 128;
    if (m0 >= Me) return;
    int n0 = blockIdx.x * 128;

    extern __shared__ char smem[];
    uint32_t sbase = smem_u32(smem);
    int tid = threadIdx.x;

    // A cp.async mapping: 512 16B segs per array, 2 per thread
    int seg0 = tid * 2, seg1 = tid * 2 + 1;
    int r0 = seg0 >> 2, j0 = seg0 & 3;
    int r1 = seg1 >> 2, j1 = seg1 & 3;
    int am0 = m0 + r0, am1 = m0 + r1;
    int av0 = (am0 < Me) ? 16 : 0, av1 = (am1 < Me) ? 16 : 0;
    size_t ar0 = 0, ar1 = 0;
    if (av0) ar0 = (size_t)(agather ? agather[rb + am0] : (rb + am0)) * K;
    if (av1) ar1 = (size_t)(agather ? agather[rb + am1] : (rb + am1)) * K;
    uint32_t dA0 = r0 * 80 + j0 * 16, dA1 = r1 * 80 + j1 * 16;

    auto issue_chunk = [&](int c, int buf) {
        uint32_t sb = sbase + buf * 40960;
        size_t kof = (size_t)c * 32;
        cp16(sb + dA0,         Ahi + ar0 + kof + j0 * 8, av0);
        cp16(sb + dA1,         Ahi + ar1 + kof + j1 * 8, av1);
        cp16(sb + 10240 + dA0, Alo + ar0 + kof + j0 * 8, av0);
        cp16(sb + 10240 + dA1, Alo + ar1 + kof + j1 * 8, av1);
        // B: 32 rows x 128 fp32, 1024 segs, 4 per thread
#pragma unroll
        for (int q = 0; q < 4; q++) {
            int s = tid + q * 256;
            int br = s >> 5, cseg = s & 31;
            cp16(sb + 20480 + br * 528 + cseg * 16,
                 Bp + (size_t)(kof + br) * N + n0 + cseg * 4, 16);
        }
        asm volatile("cp.async.commit_group;");
    };

    int lane = tid & 31, warp = tid >> 5;
    int wm = warp >> 1, wn = warp & 1;
    int g = lane >> 2, t = lane & 3;

    float acc[2][8][4];
#pragma unroll
    for (int m = 0; m < 2; m++)
#pragma unroll
        for (int nt = 0; nt < 8; nt++)
#pragma unroll
            for (int i = 0; i < 4; i++) acc[m][nt][i] = 0.f;

    int nch = K / 32;
    issue_chunk(0, 0);
    if (nch > 1) issue_chunk(1, 1);

    for (int c = 0; c < nch; c++) {
        if (c + 1 < nch) asm volatile("cp.async.wait_group 1;");
        else             asm volatile("cp.async.wait_group 0;");
        __syncthreads();
        uint32_t sb = sbase + (c & 1) * 40960;
#pragma unroll
        for (int ks = 0; ks < 2; ks++) {
            uint32_t Ah[2][4], Al[2][4];
#pragma unroll
            for (int m = 0; m < 2; m++) {
                uint32_t ra = sb + (uint32_t)((wm * 32 + m * 16 + g) * 80 + ks * 32 + t * 4);
                Ah[m][0] = lds32(ra);
                Ah[m][1] = lds32(ra + 640);
                Ah[m][2] = lds32(ra + 16);
                Ah[m][3] = lds32(ra + 656);
                Al[m][0] = lds32(ra + 10240);
                Al[m][1] = lds32(ra + 10880);
                Al[m][2] = lds32(ra + 10256);
                Al[m][3] = lds32(ra + 10896);
            }
            uint32_t bbase = sb + 20480 + (uint32_t)((ks * 16 + 2 * t) * 528 + (wn * 64 + g) * 4);
#pragma unroll
            for (int nt = 0; nt < 8; nt++) {
                uint32_t ba = bbase + nt * 32;
                float f00 = ldsf(ba), f01 = ldsf(ba + 528);
                float f10 = ldsf(ba + 8 * 528), f11 = ldsf(ba + 9 * 528);
                uint32_t bh0, bl0, bh1, bl1;
                splitpack2(f00, f01, bh0, bl0);
                splitpack2(f10, f11, bh1, bl1);
#pragma unroll
                for (int m = 0; m < 2; m++) {
                    mma_bf16(acc[m][nt], Ah[m], bh0, bh1);
                    mma_bf16(acc[m][nt], Ah[m], bl0, bl1);
                    mma_bf16(acc[m][nt], Al[m], bh0, bh1);
                }
            }
        }
        __syncthreads();
        if (c + 2 < nch) issue_chunk(c + 2, c & 1);
    }

#pragma unroll
    for (int m = 0; m < 2; m++) {
        int rlow = m0 + wm * 32 + m * 16 + g;
        int rhigh = rlow + 8;
        int crl = 0, crh = 0;
        float scl = 1.f, sch = 1.f;
        bool okl = rlow < Me, okh = rhigh < Me;
        if (okl) {
            crl = cscatter ? cscatter[rb + rlow] : (rb + rlow);
            if (rscale) scl = rscale[rb + rlow];
        }
        if (okh) {
            crh = cscatter ? cscatter[rb + rhigh] : (rb + rhigh);
            if (rscale) sch = rscale[rb + rhigh];
        }
#pragma unroll
        for (int nt = 0; nt < 8; nt++) {
            int col = n0 + wn * 64 + nt * 8 + t * 2;
            float* a = acc[m][nt];
            if (okl) {
                size_t b = (size_t)crl * ldc + col;
                float v0 = a[0] * scl, v1 = a[1] * scl;
                if (addv) { v0 += addv[b]; v1 += addv[b + 1]; }
                C[b] = v0;
                C[b + 1] = v1;
            }
            if (okh) {
                size_t b = (size_t)crh * ldc + col;
                float v2 = a[2] * sch, v3 = a[3] * sch;
                if (addv) { v2 += addv[b]; v3 += addv[b + 1]; }
                C[b] = v2;
                C[b + 1] = v3;
            }
        }
    }
}

// ===================== SIMT sgemm (router only) =====================
__global__ __launch_bounds__(256) void sgemm_k(
    const float* __restrict__ A, const float* __restrict__ B, float* __restrict__ C,
    int M, int N, int K) {
    __shared__ float As[8][128];
    __shared__ float Bs[8][128];
    int m0 = blockIdx.y * 128;
    int n0 = blockIdx.x * 128;
    int tid = threadIdx.x;
    int tx = tid & 15, ty = tid >> 4;
    int a_i = tid >> 1;
    int a_j = (tid & 1) * 4;
    const float* Arow = A + (size_t)(m0 + a_i) * K;
    int b_i = tid >> 5;
    int b_j = (tid & 31) * 4;
    bool bok = (n0 + b_j) < N;
    float acc[8][8];
#pragma unroll
    for (int a = 0; a < 8; a++)
#pragma unroll
        for (int b = 0; b < 8; b++) acc[a][b] = 0.f;
    for (int k0 = 0; k0 < K; k0 += 8) {
        float4 av = *(const float4*)(Arow + k0 + a_j);
        As[a_j + 0][a_i] = av.x;
        As[a_j + 1][a_i] = av.y;
        As[a_j + 2][a_i] = av.z;
        As[a_j + 3][a_i] = av.w;
        float4 bv = make_float4(0.f, 0.f, 0.f, 0.f);
        if (bok) bv = *(const float4*)(B + (size_t)(k0 + b_i) * N + n0 + b_j);
        *(float4*)&Bs[b_i][b_j] = bv;
        __syncthreads();
#pragma unroll
        for (int j = 0; j < 8; ++j) {
            float ra[8], rbv[8];
#pragma unroll
            for (int a = 0; a < 8; a++) ra[a] = As[j][ty * 8 + a];
#pragma unroll
            for (int b = 0; b < 8; b++) rbv[b] = Bs[j][tx * 8 + b];
#pragma unroll
            for (int a = 0; a < 8; a++)
#pragma unroll
                for (int b = 0; b < 8; b++) acc[a][b] += ra[a] * rbv[b];
        }
        __syncthreads();
    }
#pragma unroll
    for (int a = 0; a < 8; a++) {
        int r = m0 + ty * 8 + a;
        float* Crow = C + (size_t)r * N;
#pragma unroll
        for (int b = 0; b < 8; b++) {
            int ccol = n0 + tx * 8 + b;
            if (ccol < N) Crow[ccol] = acc[a][b];
        }
    }
}

// ===================== router top-8 =====================
__global__ __launch_bounds__(256) void topk_k(const float* __restrict__ logits,
                                              int* __restrict__ idx,
                                              float* __restrict__ wts) {
    int t = blockIdx.x * 8 + (threadIdx.x >> 5);
    int lane = threadIdx.x & 31;
    if (t >= T_TOK) return;
    const float* lr = logits + (size_t)t * NE;
    float v0 = lr[lane], v1 = lr[lane + 32];
    float selv[TOPK];
    int seli[TOPK];
    for (int s = 0; s < TOPK; s++) {
        float bv = v0;
        int bi = lane;
        if (v1 > bv) { bv = v1; bi = lane + 32; }
        for (int off = 16; off > 0; off >>= 1) {
            float ov = __shfl_xor_sync(0xffffffffu, bv, off);
            int oi = __shfl_xor_sync(0xffffffffu, bi, off);
            if (ov > bv || (ov == bv && oi < bi)) { bv = ov; bi = oi; }
        }
        selv[s] = bv;
        seli[s] = bi;
        if (bi == lane) v0 = -1e30f;
        if (bi == lane + 32) v1 = -1e30f;
    }
    if (lane == 0) {
        float mx = selv[0];
        float e[TOPK], sum = 0.f;
        for (int s = 0; s < TOPK; s++) { e[s] = __expf(selv[s] - mx); sum += e[s]; }
        float inv = 1.f / sum;
        for (int s = 0; s < TOPK; s++) {
            idx[t * TOPK + s] = seli[s];
            wts[t * TOPK + s] = e[s] * inv;
        }
    }
}

// ===================== routing plumbing =====================
__global__ void zero64_k(int* c) { if (threadIdx.x < NE) c[threadIdx.x] = 0; }

__global__ void count_k(const int* __restrict__ idx, int* __restrict__ counts) {
    int i = blockIdx.x * blockDim.x + threadIdx.x;
    if (i < T_TOK * TOPK) atomicAdd(&counts[idx[i]], 1);
}

__global__ void scan_k(const int* __restrict__ counts, int* __restrict__ off,
                       int* __restrict__ cursor) {
    if (threadIdx.x == 0) {
        int s = 0;
        for (int e = 0; e < NE; e++) { off[e] = s; cursor[e] = s; s += counts[e]; }
        off[NE] = s;
    }
}

__global__ void fill_k(const int* __restrict__ idx, const float* __restrict__ wts,
                       int* __restrict__ cursor, int* __restrict__ tok,
                       int* __restrict__ crow, float* __restrict__ rsc) {
    int i = blockIdx.x * blockDim.x + threadIdx.x;
    if (i < T_TOK * TOPK) {
        int t = i >> 3;
        int e = idx[i];
        int p = atomicAdd(&cursor[e], 1);
        tok[p] = t;
        crow[p] = i;
        rsc[p] = wts[i];
    }
}

// ===================== silu(g)*u -> split bf16 act =====================
__global__ void silumul_split_k(const float* __restrict__ gu,
                                bf16* __restrict__ ahi, bf16* __restrict__ alo) {
    int i = blockIdx.x * blockDim.x + threadIdx.x;
    if (i < NROWS * FF) {
        int r = i / FF, j = i - r * FF;
        float g = gu[(size_t)r * GU_N + j];
        float u = gu[(size_t)r * GU_N + FF + j];
        float a = (g / (1.f + __expf(-g))) * u;
        bf16 h, l;
        split_bf16(a, h, l);
        ahi[i] = h;
        alo[i] = l;
    }
}

// ===================== combine 8 slots =====================
__global__ void combine_k(const float* __restrict__ part, float* __restrict__ out) {
    int i = blockIdx.x * blockDim.x + threadIdx.x;
    if (i < T_TOK * D_DIM) {
        int t = i >> 11;
        int d = i & 2047;
        float s = 0.f;
#pragma unroll
        for (int sl = 0; sl < TOPK; sl++)
            s += part[((size_t)(t * TOPK + sl)) * D_DIM + d];
        out[i] = s;
    }
}

// ===================== launch =====================
#define MMA_SMEM 81920

extern "C" void kernel_launch(void* const* d_in, const int* in_sizes, int n_in,
                              void* d_out, int out_size) {
    const int*   positions = (const int*)d_in[0];
    const float* hidden    = (const float*)d_in[1];
    const float* in_ln     = (const float*)d_in[2];
    const float* post_ln   = (const float*)d_in[3];
    const float* qns       = (const float*)d_in[4];
    const float* kns       = (const float*)d_in[5];
    const float* wq        = (const float*)d_in[6];
    const float* wk        = (const float*)d_in[7];
    const float* wv        = (const float*)d_in[8];
    const float* wo        = (const float*)d_in[9];
    const float* wr        = (const float*)d_in[10];
    const float* wg        = (const float*)d_in[11];
    const float* wu        = (const float*)d_in[12];
    const float* wd        = (const float*)d_in[13];

    float* outp   = (float*)d_out;
    float* residp = outp + (size_t)T_TOK * D_DIM;

    cudaFuncSetAttribute(mma_gemm_k, cudaFuncAttributeMaxDynamicSharedMemorySize, MMA_SMEM);
    cudaFuncSetAttribute(fattn_k, cudaFuncAttributeMaxDynamicSharedMemorySize, ATT_SMEM);

    bf16 *hn_hi, *hn_lo, *qh, *ql, *kh, *kl, *vth, *vtl;
    bf16 *ao_hi, *ao_lo, *h2n_hi, *h2n_lo, *act_hi, *act_lo;
    float *qkv, *h2n, *logits, *twt, *rsc, *gu, *part;
    int *tidx, *counts, *off, *cursor, *tok, *crow;
    cudaGetSymbolAddress((void**)&hn_hi, g_hn_hi);
    cudaGetSymbolAddress((void**)&hn_lo, g_hn_lo);
    cudaGetSymbolAddress((void**)&qkv, g_qkv);
    cudaGetSymbolAddress((void**)&qh, g_qh);
    cudaGetSymbolAddress((void**)&ql, g_ql);
    cudaGetSymbolAddress((void**)&kh, g_kh);
    cudaGetSymbolAddress((void**)&kl, g_kl);
    cudaGetSymbolAddress((void**)&vth, g_vth);
    cudaGetSymbolAddress((void**)&vtl, g_vtl);
    cudaGetSymbolAddress((void**)&ao_hi, g_ao_hi);
    cudaGetSymbolAddress((void**)&ao_lo, g_ao_lo);
    cudaGetSymbolAddress((void**)&h2n, g_h2n);
    cudaGetSymbolAddress((void**)&h2n_hi, g_h2n_hi);
    cudaGetSymbolAddress((void**)&h2n_lo, g_h2n_lo);
    cudaGetSymbolAddress((void**)&logits, g_logits);
    cudaGetSymbolAddress((void**)&tidx, g_tidx);
    cudaGetSymbolAddress((void**)&twt, g_twt);
    cudaGetSymbolAddress((void**)&counts, g_counts);
    cudaGetSymbolAddress((void**)&off, g_off);
    cudaGetSymbolAddress((void**)&cursor, g_cursor);
    cudaGetSymbolAddress((void**)&tok, g_tok);
    cudaGetSymbolAddress((void**)&crow, g_crow);
    cudaGetSymbolAddress((void**)&rsc, g_rsc);
    cudaGetSymbolAddress((void**)&gu, g_gu);
    cudaGetSymbolAddress((void**)&act_hi, g_act_hi);
    cudaGetSymbolAddress((void**)&act_lo, g_act_lo);
    cudaGetSymbolAddress((void**)&part, g_part);

    // 1. pre-attention rmsnorm (split only)
    rmsnorm_split_k<<<T_TOK, 256>>>(hidden, in_ln, nullptr, hn_hi, hn_lo);

    // 2. Q/K/V projections straight from raw fp32 weights (natural [K][N] layout),
    //    packed into qkv buffer via ldc offsets
    mma_gemm_k<<<dim3((HQ*HD)/128, T_TOK/128, 1), 256, MMA_SMEM>>>(
        hn_hi, hn_lo, wq, 0, qkv, QKV_N, T_TOK, HQ*HD, D_DIM,
        nullptr, nullptr, nullptr, nullptr, nullptr);
    mma_gemm_k<<<dim3((HKV*HD)/128, T_TOK/128, 1), 256, MMA_SMEM>>>(
        hn_hi, hn_lo, wk, 0, qkv + HQ*HD, QKV_N, T_TOK, HKV*HD, D_DIM,
        nullptr, nullptr, nullptr, nullptr, nullptr);
    mma_gemm_k<<<dim3((HKV*HD)/128, T_TOK/128, 1), 256, MMA_SMEM>>>(
        hn_hi, hn_lo, wv, 0, qkv + HQ*HD + HKV*HD, QKV_N, T_TOK, HKV*HD, D_DIM,
        nullptr, nullptr, nullptr, nullptr, nullptr);

    // 3. QK rmsnorm + rope -> split bf16; V transpose + split
    qknorm_rope_split_k<<<dim3(T_TOK, HQ + HKV), 128>>>(qkv, qns, kns, positions,
                                                        qh, ql, kh, kl);
    vtrans_split_k<<<dim3(T_TOK/32, HD/32, HKV), 256>>>(qkv, vth, vtl);

    // 4. MMA flash attention
    fattn_k<<<dim3(T_TOK/128, HQ), 256, ATT_SMEM>>>(qh, ql, kh, kl, vth, vtl,
                                                    ao_hi, ao_lo);

    // 5. O projection + residual
    mma_gemm_k<<<dim3(D_DIM/128, T_TOK/128, 1), 256, MMA_SMEM>>>(
        ao_hi, ao_lo, wo, 0, residp, D_DIM, T_TOK, D_DIM, HQ*HD,
        nullptr, nullptr, nullptr, nullptr, hidden);

    // 6. post-attention rmsnorm
    rmsnorm_split_k<<<T_TOK, 256>>>(residp, post_ln, h2n, h2n_hi, h2n_lo);

    // 7. router + top-8
    sgemm_k<<<dim3(1, T_TOK/128, 1), 256>>>(h2n, wr, logits, T_TOK, NE, D_DIM);
    topk_k<<<T_TOK / 8, 256>>>(logits, tidx, twt);

    // 8. per-expert token lists
    zero64_k<<<1, 64>>>(counts);
    count_k<<<(T_TOK * TOPK + 255) / 256, 256>>>(tidx, counts);
    scan_k<<<1, 32>>>(counts, off, cursor);
    fill_k<<<(T_TOK * TOPK + 255) / 256, 256>>>(tidx, twt, cursor, tok, crow, rsc);

    // 9. gate / up gather-GEMMs per expert (raw wg/wu, [D][F] per expert)
    mma_gemm_k<<<dim3(FF/128, 16, NE), 256, MMA_SMEM>>>(
        h2n_hi, h2n_lo, wg, (size_t)D_DIM*FF, gu, GU_N, T_TOK, FF, D_DIM,
        off, tok, nullptr, nullptr, nullptr);
    mma_gemm_k<<<dim3(FF/128, 16, NE), 256, MMA_SMEM>>>(
        h2n_hi, h2n_lo, wu, (size_t)D_DIM*FF, gu + FF, GU_N, T_TOK, FF, D_DIM,
        off, tok, nullptr, nullptr, nullptr);

    // 10. silu(g)*u split
    silumul_split_k<<<(NROWS * FF + 255) / 256, 256>>>(gu, act_hi, act_lo);

    // 11. down scatter-GEMM per expert (raw wd, [F][D] per expert)
    mma_gemm_k<<<dim3(D_DIM/128, 16, NE), 256, MMA_SMEM>>>(
        act_hi, act_lo, wd, (size_t)FF*D_DIM, part, D_DIM, T_TOK, D_DIM, FF,
        off, nullptr, crow, rsc, nullptr);

    // 12. combine
    combine_k<<<(T_TOK * D_DIM + 255) / 256, 256>>>(part, outp);
}

// round 7
// speedup vs baseline: 3.6619x; 1.2138x over previous
#include <cuda_runtime.h>
#include <cuda_bf16.h>
#include <math.h>
#include <stdint.h>

// Problem constants
#define T_TOK 2048
#define D_DIM 2048
#define HQ 32
#define HKV 4
#define HD 128
#define NE 64
#define TOPK 8
#define FF 768
#define NROWS (T_TOK*TOPK)
#define QKV_N (HQ*HD + 2*HKV*HD)   // 5120
#define GU_N  (2*FF)               // 1536

typedef __nv_bfloat16 bf16;

__device__ __forceinline__ uint32_t smem_u32(const void* p) {
    uint32_t a;
    asm("{ .reg .u64 t; cvta.to.shared.u64 t, %1; cvt.u32.u64 %0, t; }" : "=r"(a) : "l"(p));
    return a;
}
__device__ __forceinline__ uint32_t lds32(uint32_t addr) {
    uint32_t v;
    asm volatile("ld.shared.b32 %0, [%1];" : "=r"(v) : "r"(addr));
    return v;
}
__device__ __forceinline__ float ldsf(uint32_t addr) {
    float v;
    asm volatile("ld.shared.f32 %0, [%1];" : "=f"(v) : "r"(addr));
    return v;
}
__device__ __forceinline__ void cp16(uint32_t dst, const void* src, int sz) {
    asm volatile("cp.async.cg.shared.global [%0], [%1], 16, %2;"
                 :: "r"(dst), "l"(src), "r"(sz));
}
__device__ __forceinline__ void mma_bf16(float* d, const uint32_t* a, uint32_t b0, uint32_t b1) {
    asm volatile("mma.sync.aligned.m16n8k16.row.col.f32.bf16.bf16.f32 "
                 "{%0,%1,%2,%3}, {%4,%5,%6,%7}, {%8,%9}, {%0,%1,%2,%3};"
                 : "+f"(d[0]), "+f"(d[1]), "+f"(d[2]), "+f"(d[3])
                 : "r"(a[0]), "r"(a[1]), "r"(a[2]), "r"(a[3]), "r"(b0), "r"(b1));
}
__device__ __forceinline__ void split_bf16(float x, bf16& h, bf16& l) {
    h = __float2bfloat16(x);
    l = __float2bfloat16(x - __bfloat162float(h));
}
__device__ __forceinline__ uint32_t pack_bf16(bf16 a, bf16 b) {
    return (uint32_t)__bfloat16_as_ushort(a) | ((uint32_t)__bfloat16_as_ushort(b) << 16);
}
__device__ __forceinline__ uint32_t pack2f(float a, float b) {
    return pack_bf16(__float2bfloat16(a), __float2bfloat16(b));
}
__device__ __forceinline__ uint32_t pack2f_lo(float a, float b, uint32_t hipair) {
    float ha = __bfloat162float(__ushort_as_bfloat16((unsigned short)(hipair & 0xFFFF)));
    float hb = __bfloat162float(__ushort_as_bfloat16((unsigned short)(hipair >> 16)));
    return pack_bf16(__float2bfloat16(a - ha), __float2bfloat16(b - hb));
}
__device__ __forceinline__ void splitpack2(float f0, float f1, uint32_t& h, uint32_t& l) {
    float h0 = __bfloat162float(__float2bfloat16(f0));
    float h1 = __bfloat162float(__float2bfloat16(f1));
    asm("cvt.rn.bf16x2.f32 %0, %1, %2;" : "=r"(h) : "f"(f1), "f"(f0));
    float l0 = f0 - h0, l1 = f1 - h1;
    asm("cvt.rn.bf16x2.f32 %0, %1, %2;" : "=r"(l) : "f"(l1), "f"(l0));
}

// ===================== scratch =====================
__device__ bf16 g_hn_hi[(size_t)T_TOK * D_DIM];
__device__ bf16 g_hn_lo[(size_t)T_TOK * D_DIM];
__device__ float g_qkv[(size_t)T_TOK * QKV_N];
__device__ bf16 g_qh[(size_t)T_TOK * HQ*HD];
__device__ bf16 g_ql[(size_t)T_TOK * HQ*HD];
__device__ bf16 g_kh[(size_t)HKV * T_TOK * HD];
__device__ bf16 g_kl[(size_t)HKV * T_TOK * HD];
__device__ bf16 g_vth[(size_t)HKV * HD * T_TOK];
__device__ bf16 g_vtl[(size_t)HKV * HD * T_TOK];
__device__ bf16 g_ao_hi[(size_t)T_TOK * (HQ*HD)];
__device__ bf16 g_ao_lo[(size_t)T_TOK * (HQ*HD)];
__device__ bf16 g_h2n_hi[(size_t)T_TOK * D_DIM];
__device__ bf16 g_h2n_lo[(size_t)T_TOK * D_DIM];
__device__ float g_logits[T_TOK*NE];
__device__ int   g_tidx[T_TOK*TOPK];
__device__ float g_twt[T_TOK*TOPK];
__device__ int   g_counts[NE];
__device__ int   g_off[NE+1];
__device__ int   g_cursor[NE];
__device__ int   g_tok[NROWS];
__device__ int   g_crow[NROWS];
__device__ float g_rsc[NROWS];
__device__ float g_gu[(size_t)NROWS * GU_N];
__device__ bf16 g_act_hi[(size_t)NROWS * FF];
__device__ bf16 g_act_lo[(size_t)NROWS * FF];
__device__ float g_part[(size_t)NROWS * D_DIM];

// ===================== rmsnorm + bf16 split =====================
__global__ __launch_bounds__(256) void rmsnorm_split_k(
    const float* __restrict__ x, const float* __restrict__ sc,
    bf16* __restrict__ hi, bf16* __restrict__ lo) {
    int row = blockIdx.x;
    const float* xr = x + (size_t)row * D_DIM;
    float ss = 0.f;
    for (int i = threadIdx.x; i < D_DIM; i += 256) { float v = xr[i]; ss += v * v; }
    for (int o = 16; o > 0; o >>= 1) ss += __shfl_xor_sync(0xffffffffu, ss, o);
    __shared__ float sw[8];
    if ((threadIdx.x & 31) == 0) sw[threadIdx.x >> 5] = ss;
    __syncthreads();
    float tot = 0.f;
#pragma unroll
    for (int i = 0; i < 8; i++) tot += sw[i];
    float inv = rsqrtf(tot * (1.f / D_DIM) + 1e-6f);
    size_t base = (size_t)row * D_DIM;
    for (int i = threadIdx.x; i < D_DIM; i += 256) {
        float v = xr[i] * inv * sc[i];
        bf16 h, l;
        split_bf16(v, h, l);
        hi[base + i] = h;
        lo[base + i] = l;
    }
}

// ===================== qk norm + rope -> split bf16 =====================
__global__ __launch_bounds__(128) void qknorm_rope_split_k(
    const float* __restrict__ qkv,
    const float* __restrict__ qns, const float* __restrict__ kns,
    const int* __restrict__ pos,
    bf16* __restrict__ qh, bf16* __restrict__ ql,
    bf16* __restrict__ kh, bf16* __restrict__ kl) {
    int t = blockIdx.x, h = blockIdx.y;  // 0..31 q, 32..35 k
    bool isq = h < HQ;
    const float* xr;
    const float* nsc;
    if (isq) { xr = qkv + (size_t)t * QKV_N + h * HD; nsc = qns; }
    else     { xr = qkv + (size_t)t * QKV_N + HQ*HD + (h - HQ) * HD; nsc = kns; }
    int d = threadIdx.x;
    float v = xr[d];
    float ss = v * v;
    for (int o = 16; o > 0; o >>= 1) ss += __shfl_xor_sync(0xffffffffu, ss, o);
    __shared__ float sw[4];
    if ((d & 31) == 0) sw[d >> 5] = ss;
    __syncthreads();
    float tot = sw[0] + sw[1] + sw[2] + sw[3];
    float xn = v * rsqrtf(tot * (1.f / HD) + 1e-6f) * nsc[d];
    __shared__ float sx[HD];
    sx[d] = xn;
    __syncthreads();
    int dr = d & 63;
    float inv_freq = expf(-(float)dr * 0.21586735246819178f);
    float ang = (float)pos[t] * inv_freq;
    float sn, cs;
    sincosf(ang, &sn, &cs);
    float val = (d < 64) ? (sx[dr] * cs - sx[dr + 64] * sn)
                         : (sx[dr + 64] * cs + sx[dr] * sn);
    bf16 hh, ll;
    split_bf16(val, hh, ll);
    if (isq) {
        size_t o = (size_t)t * (HQ*HD) + h * HD + d;
        qh[o] = hh;
        ql[o] = ll;
    } else {
        size_t o = ((size_t)(h - HQ) * T_TOK + t) * HD + d;
        kh[o] = hh;
        kl[o] = ll;
    }
}

// ===================== V transpose + split: [t][d] -> [kvh][d][t] =====================
__global__ __launch_bounds__(256) void vtrans_split_k(
    const float* __restrict__ qkv, bf16* __restrict__ vth, bf16* __restrict__ vtl) {
    int t0 = blockIdx.x * 32, d0 = blockIdx.y * 32, kvh = blockIdx.z;
    __shared__ float tb[32][33];
    int tx = threadIdx.x & 31, ty = threadIdx.x >> 5;
    const float* src = qkv + HQ*HD + HKV*HD + kvh * HD;
    for (int j = ty; j < 32; j += 8) tb[j][tx] = src[(size_t)(t0 + j) * QKV_N + d0 + tx];
    __syncthreads();
    int px = threadIdx.x & 15, py = threadIdx.x >> 4;
    for (int j = py; j < 32; j += 16) {
        float v0 = tb[2 * px][j], v1 = tb[2 * px + 1][j];
        bf16 h0, l0, h1, l1;
        split_bf16(v0, h0, l0);
        split_bf16(v1, h1, l1);
        size_t o = ((size_t)kvh * HD + d0 + j) * T_TOK + t0 + 2 * px;
        *(uint32_t*)(vth + o) = pack_bf16(h0, h1);
        *(uint32_t*)(vtl + o) = pack_bf16(l0, l1);
    }
}

// ===================== MMA flash attention (unchanged) =====================
#define ATT_SMEM 163840
__global__ __launch_bounds__(256) void fattn_k(
    const bf16* __restrict__ Qhi, const bf16* __restrict__ Qlo,
    const bf16* __restrict__ Khi, const bf16* __restrict__ Klo,
    const bf16* __restrict__ Vthi, const bf16* __restrict__ Vtlo,
    bf16* __restrict__ Ohi, bf16* __restrict__ Olo) {
    int qb = blockIdx.x, h = blockIdx.y;
    int kvh = h >> 3;
    int tid = threadIdx.x, lane = tid & 31, w = tid >> 5;
    int g = lane >> 2, t = lane & 3;
    extern __shared__ char smem[];
    uint32_t sb = smem_u32(smem);
    int qbase = qb * 128;
    const float scale = 0.08838834764831845f;

    {
        const bf16* qhp = Qhi + (size_t)qbase * (HQ*HD) + h * HD;
        const bf16* qlp = Qlo + (size_t)qbase * (HQ*HD) + h * HD;
        for (int s = tid; s < 2048; s += 256) {
            int r = s >> 4, j = s & 15;
            uint32_t dst = (uint32_t)((j >> 2) * 10240 + r * 80 + (j & 3) * 16);
            cp16(sb + dst, qhp + (size_t)r * (HQ*HD) + j * 8, 16);
            cp16(sb + 40960 + dst, qlp + (size_t)r * (HQ*HD) + j * 8, 16);
        }
        asm volatile("cp.async.commit_group;");
    }
    int ntiles = qb * 4 + 4;
    const bf16* khp = Khi + (size_t)kvh * T_TOK * HD;
    const bf16* klp = Klo + (size_t)kvh * T_TOK * HD;
    const bf16* vhp = Vthi + (size_t)kvh * HD * T_TOK;
    const bf16* vlp = Vtlo + (size_t)kvh * HD * T_TOK;

    auto issue_kv = [&](int kt, int buf) {
        uint32_t base = sb + 81920 + buf * 40960;
        for (int s = tid; s < 512; s += 256) {
            int r = s >> 4, j = s & 15;
            uint32_t dst = (uint32_t)((j >> 2) * 2560 + r * 80 + (j & 3) * 16);
            cp16(base + dst,         khp + (size_t)(kt * 32 + r) * HD + j * 8, 16);
            cp16(base + 10240 + dst, klp + (size_t)(kt * 32 + r) * HD + j * 8, 16);
        }
        for (int s = tid; s < 512; s += 256) {
            int d = s >> 2, j = s & 3;
            uint32_t dst = (uint32_t)(d * 80 + j * 16);
            cp16(base + 20480 + dst, vhp + (size_t)d * T_TOK + kt * 32 + j * 8, 16);
            cp16(base + 30720 + dst, vlp + (size_t)d * T_TOK + kt * 32 + j * 8, 16);
        }
        asm volatile("cp.async.commit_group;");
    };
    issue_kv(0, 0);
    if (ntiles > 1) issue_kv(1, 1);

    float o[16][4];
#pragma unroll
    for (int i = 0; i < 16; i++)
#pragma unroll
        for (int k = 0; k < 4; k++) o[i][k] = 0.f;
    float m0 = -1e30f, m1 = -1e30f, l0 = 0.f, l1 = 0.f;
    int wr = w * 16;
    int row0 = qbase + wr + g, row1 = row0 + 8;

    for (int kt = 0; kt < ntiles; kt++) {
        if (kt + 1 < ntiles) asm volatile("cp.async.wait_group 1;");
        else                 asm volatile("cp.async.wait_group 0;");
        __syncthreads();
        uint32_t kb = sb + 81920 + (kt & 1) * 40960;
        bool active = (kt * 32 <= qbase + wr + 15);
        if (active) {
            float s[4][4];
#pragma unroll
            for (int nt = 0; nt < 4; nt++)
#pragma unroll
                for (int i = 0; i < 4; i++) s[nt][i] = 0.f;
#pragma unroll
            for (int ks = 0; ks < 8; ks++) {
                uint32_t ra = sb + (ks >> 1) * 10240 + (wr + g) * 80 + (ks & 1) * 32 + t * 4;
                uint32_t Ah[4], Al[4];
                Ah[0] = lds32(ra);
                Ah[1] = lds32(ra + 640);
                Ah[2] = lds32(ra + 16);
                Ah[3] = lds32(ra + 656);
                Al[0] = lds32(ra + 40960);
                Al[1] = lds32(ra + 41600);
                Al[2] = lds32(ra + 40976);
                Al[3] = lds32(ra + 41616);
#pragma unroll
                for (int nt = 0; nt < 4; nt++) {
                    uint32_t rk = kb + (ks >> 1) * 2560 + (nt * 8 + g) * 80 + (ks & 1) * 32 + t * 4;
                    uint32_t bh0 = lds32(rk), bh1 = lds32(rk + 16);
                    uint32_t bl0 = lds32(rk + 10240), bl1 = lds32(rk + 10256);
                    mma_bf16(s[nt], Ah, bh0, bh1);
                    mma_bf16(s[nt], Ah, bl0, bl1);
                    mma_bf16(s[nt], Al, bh0, bh1);
                }
            }
#pragma unroll
            for (int nt = 0; nt < 4; nt++) {
                int c0 = kt * 32 + nt * 8 + 2 * t;
                s[nt][0] = (c0     <= row0) ? s[nt][0] * scale : -1e30f;
                s[nt][1] = (c0 + 1 <= row0) ? s[nt][1] * scale : -1e30f;
                s[nt][2] = (c0     <= row1) ? s[nt][2] * scale : -1e30f;
                s[nt][3] = (c0 + 1 <= row1) ? s[nt][3] * scale : -1e30f;
            }
            float rm0 = -1e30f, rm1 = -1e30f;
#pragma unroll
            for (int nt = 0; nt < 4; nt++) {
                rm0 = fmaxf(rm0, fmaxf(s[nt][0], s[nt][1]));
                rm1 = fmaxf(rm1, fmaxf(s[nt][2], s[nt][3]));
            }
            rm0 = fmaxf(rm0, __shfl_xor_sync(0xffffffffu, rm0, 1));
            rm0 = fmaxf(rm0, __shfl_xor_sync(0xffffffffu, rm0, 2));
            rm1 = fmaxf(rm1, __shfl_xor_sync(0xffffffffu, rm1, 1));
            rm1 = fmaxf(rm1, __shfl_xor_sync(0xffffffffu, rm1, 2));
            float mn0 = fmaxf(m0, rm0), mn1 = fmaxf(m1, rm1);
            float cor0 = __expf(m0 - mn0), cor1 = __expf(m1 - mn1);
            m0 = mn0;
            m1 = mn1;
            float ps0 = 0.f, ps1 = 0.f;
#pragma unroll
            for (int nt = 0; nt < 4; nt++) {
                s[nt][0] = __expf(s[nt][0] - mn0);
                s[nt][1] = __expf(s[nt][1] - mn0);
                s[nt][2] = __expf(s[nt][2] - mn1);
                s[nt][3] = __expf(s[nt][3] - mn1);
                ps0 += s[nt][0] + s[nt][1];
                ps1 += s[nt][2] + s[nt][3];
            }
            ps0 += __shfl_xor_sync(0xffffffffu, ps0, 1);
            ps0 += __shfl_xor_sync(0xffffffffu, ps0, 2);
            ps1 += __shfl_xor_sync(0xffffffffu, ps1, 1);
            ps1 += __shfl_xor_sync(0xffffffffu, ps1, 2);
            l0 = l0 * cor0 + ps0;
            l1 = l1 * cor1 + ps1;
#pragma unroll
            for (int i = 0; i < 16; i++) {
                o[i][0] *= cor0;
                o[i][1] *= cor0;
                o[i][2] *= cor1;
                o[i][3] *= cor1;
            }
            uint32_t Ph[2][4], Pl[2][4];
#pragma unroll
            for (int kk = 0; kk < 2; kk++) {
                int n0t = 2 * kk;
                Ph[kk][0] = pack2f(s[n0t][0], s[n0t][1]);
                Ph[kk][1] = pack2f(s[n0t][2], s[n0t][3]);
                Ph[kk][2] = pack2f(s[n0t + 1][0], s[n0t + 1][1]);
                Ph[kk][3] = pack2f(s[n0t + 1][2], s[n0t + 1][3]);
                Pl[kk][0] = pack2f_lo(s[n0t][0], s[n0t][1], Ph[kk][0]);
                Pl[kk][1] = pack2f_lo(s[n0t][2], s[n0t][3], Ph[kk][1]);
                Pl[kk][2] = pack2f_lo(s[n0t + 1][0], s[n0t + 1][1], Ph[kk][2]);
                Pl[kk][3] = pack2f_lo(s[n0t + 1][2], s[n0t + 1][3], Ph[kk][3]);
            }
#pragma unroll
            for (int kk = 0; kk < 2; kk++) {
#pragma unroll
                for (int nt2 = 0; nt2 < 16; nt2++) {
                    uint32_t rv = kb + 20480 + (nt2 * 8 + g) * 80 + kk * 32 + t * 4;
                    uint32_t bh0 = lds32(rv), bh1 = lds32(rv + 16);
                    uint32_t bl0 = lds32(rv + 10240), bl1 = lds32(rv + 10256);
                    mma_bf16(o[nt2], Ph[kk], bh0, bh1);
                    mma_bf16(o[nt2], Ph[kk], bl0, bl1);
                    mma_bf16(o[nt2], Pl[kk], bh0, bh1);
                }
            }
        }
        __syncthreads();
        if (kt + 2 < ntiles) issue_kv(kt + 2, kt & 1);
    }
    float il0 = 1.f / l0, il1 = 1.f / l1;
#pragma unroll
    for (int nt2 = 0; nt2 < 16; nt2++) {
        int d = nt2 * 8 + 2 * t;
        float v0 = o[nt2][0] * il0, v1 = o[nt2][1] * il0;
        float v2 = o[nt2][2] * il1, v3 = o[nt2][3] * il1;
        size_t b0 = (size_t)row0 * (HQ*HD) + h * HD + d;
        size_t b1 = (size_t)row1 * (HQ*HD) + h * HD + d;
        uint32_t h0 = pack2f(v0, v1), h1p = pack2f(v2, v3);
        *(uint32_t*)(Ohi + b0) = h0;
        *(uint32_t*)(Ohi + b1) = h1p;
        *(uint32_t*)(Olo + b0) = pack2f_lo(v0, v1, h0);
        *(uint32_t*)(Olo + b1) = pack2f_lo(v2, v3, h1p);
    }
}

// ===================== HMMA bf16x3 GEMM, multi-weight routed =====================
// blockIdx.x selects among up to 3 B weights: tiles [0,t0) -> B0, [t0,t0+t1) -> B1,
// rest -> B2. C column = blockIdx.x*128. B raw fp32 [K][ldb], split on the fly.
// Per-buffer smem: Ahi @0 (10240) | Alo @10240 | Bf32 @20480 (16896) = 37376; x2 buffers.
#define MMA_SMEM 74752
__global__ __launch_bounds__(256, 2) void mma_gemm_k(
    const bf16* __restrict__ Ahi, const bf16* __restrict__ Alo,
    const float* __restrict__ B0, const float* __restrict__ B1,
    const float* __restrict__ B2,
    int t0, int t1, int ldb0, int ldb1, int ldb2,
    size_t bStrideE, int nValid,
    float* __restrict__ C, int ldc,
    int M, int K,
    const int* __restrict__ eoff, const int* __restrict__ agather,
    const int* __restrict__ cscatter, const float* __restrict__ rscale,
    const float* __restrict__ addv) {
    int rb = 0, Me = M;
    int bx = blockIdx.x;
    const float* Bp;
    int ldb, lt;
    if (bx < t0)           { Bp = B0; ldb = ldb0; lt = bx; }
    else if (bx < t0 + t1) { Bp = B1; ldb = ldb1; lt = bx - t0; }
    else                   { Bp = B2; ldb = ldb2; lt = bx - t0 - t1; }
    if (eoff) {
        int e = blockIdx.z;
        rb = eoff[e];
        Me = eoff[e + 1] - rb;
        Bp += (size_t)e * bStrideE;
    }
    int m0 = blockIdx.y * 128;
    if (m0 >= Me) return;
    int n0 = lt * 128;        // column within this weight
    int ccol = bx * 128;      // column within C

    extern __shared__ char smem[];
    uint32_t sbase = smem_u32(smem);
    int tid = threadIdx.x;

    // A cp.async mapping: 512 16B segs per array, 2 per thread
    int seg0 = tid * 2, seg1 = tid * 2 + 1;
    int r0 = seg0 >> 2, j0 = seg0 & 3;
    int r1 = seg1 >> 2, j1 = seg1 & 3;
    int am0 = m0 + r0, am1 = m0 + r1;
    int av0 = (am0 < Me) ? 16 : 0, av1 = (am1 < Me) ? 16 : 0;
    size_t ar0 = 0, ar1 = 0;
    if (av0) ar0 = (size_t)(agather ? agather[rb + am0] : (rb + am0)) * K;
    if (av1) ar1 = (size_t)(agather ? agather[rb + am1] : (rb + am1)) * K;
    uint32_t dA0 = r0 * 80 + j0 * 16, dA1 = r1 * 80 + j1 * 16;

    auto issue_chunk = [&](int c, int buf) {
        uint32_t sb = sbase + buf * 37376;
        size_t kof = (size_t)c * 32;
        cp16(sb + dA0,         Ahi + ar0 + kof + j0 * 8, av0);
        cp16(sb + dA1,         Ahi + ar1 + kof + j1 * 8, av1);
        cp16(sb + 10240 + dA0, Alo + ar0 + kof + j0 * 8, av0);
        cp16(sb + 10240 + dA1, Alo + ar1 + kof + j1 * 8, av1);
        // B: 32 rows x 128 fp32, 1024 segs, 4 per thread; col guard vs nValid
#pragma unroll
        for (int q = 0; q < 4; q++) {
            int s = tid + q * 256;
            int br = s >> 5, cseg = s & 31;
            int bsz = (cseg * 4 + 4 <= nValid) ? 16 : 0;
            const float* bsrc = bsz ? (Bp + (size_t)(kof + br) * ldb + n0 + cseg * 4) : Bp;
            cp16(sb + 20480 + br * 528 + cseg * 16, bsrc, bsz);
        }
        asm volatile("cp.async.commit_group;");
    };

    int lane = tid & 31, warp = tid >> 5;
    int wm = warp >> 1, wn = warp & 1;
    int g = lane >> 2, t = lane & 3;

    float acc[2][8][4];
#pragma unroll
    for (int m = 0; m < 2; m++)
#pragma unroll
        for (int nt = 0; nt < 8; nt++)
#pragma unroll
            for (int i = 0; i < 4; i++) acc[m][nt][i] = 0.f;

    int nch = K / 32;
    issue_chunk(0, 0);
    if (nch > 1) issue_chunk(1, 1);

    for (int c = 0; c < nch; c++) {
        if (c + 1 < nch) asm volatile("cp.async.wait_group 1;");
        else             asm volatile("cp.async.wait_group 0;");
        __syncthreads();
        uint32_t sb = sbase + (c & 1) * 37376;
#pragma unroll
        for (int ks = 0; ks < 2; ks++) {
            uint32_t Ah[2][4], Al[2][4];
#pragma unroll
            for (int m = 0; m < 2; m++) {
                uint32_t ra = sb + (uint32_t)((wm * 32 + m * 16 + g) * 80 + ks * 32 + t * 4);
                Ah[m][0] = lds32(ra);
                Ah[m][1] = lds32(ra + 640);
                Ah[m][2] = lds32(ra + 16);
                Ah[m][3] = lds32(ra + 656);
                Al[m][0] = lds32(ra + 10240);
                Al[m][1] = lds32(ra + 10880);
                Al[m][2] = lds32(ra + 10256);
                Al[m][3] = lds32(ra + 10896);
            }
            uint32_t bbase = sb + 20480 + (uint32_t)((ks * 16 + 2 * t) * 528 + (wn * 64 + g) * 4);
#pragma unroll
            for (int nt = 0; nt < 8; nt++) {
                uint32_t ba = bbase + nt * 32;
                float f00 = ldsf(ba), f01 = ldsf(ba + 528);
                float f10 = ldsf(ba + 8 * 528), f11 = ldsf(ba + 9 * 528);
                uint32_t bh0, bl0, bh1, bl1;
                splitpack2(f00, f01, bh0, bl0);
                splitpack2(f10, f11, bh1, bl1);
#pragma unroll
                for (int m = 0; m < 2; m++) {
                    mma_bf16(acc[m][nt], Ah[m], bh0, bh1);
                    mma_bf16(acc[m][nt], Ah[m], bl0, bl1);
                    mma_bf16(acc[m][nt], Al[m], bh0, bh1);
                }
            }
        }
        __syncthreads();
        if (c + 2 < nch) issue_chunk(c + 2, c & 1);
    }

#pragma unroll
    for (int m = 0; m < 2; m++) {
        int rlow = m0 + wm * 32 + m * 16 + g;
        int rhigh = rlow + 8;
        int crl = 0, crh = 0;
        float scl = 1.f, sch = 1.f;
        bool okl = rlow < Me, okh = rhigh < Me;
        if (okl) {
            crl = cscatter ? cscatter[rb + rlow] : (rb + rlow);
            if (rscale) scl = rscale[rb + rlow];
        }
        if (okh) {
            crh = cscatter ? cscatter[rb + rhigh] : (rb + rhigh);
            if (rscale) sch = rscale[rb + rhigh];
        }
#pragma unroll
        for (int nt = 0; nt < 8; nt++) {
            int lcol = wn * 64 + nt * 8 + t * 2;
            if (lcol >= nValid) continue;
            int col = ccol + lcol;
            float* a = acc[m][nt];
            if (okl) {
                size_t b = (size_t)crl * ldc + col;
                float v0 = a[0] * scl, v1 = a[1] * scl;
                if (addv) { v0 += addv[b]; v1 += addv[b + 1]; }
                C[b] = v0;
                C[b + 1] = v1;
            }
            if (okh) {
                size_t b = (size_t)crh * ldc + col;
                float v2 = a[2] * sch, v3 = a[3] * sch;
                if (addv) { v2 += addv[b]; v3 += addv[b + 1]; }
                C[b] = v2;
                C[b + 1] = v3;
            }
        }
    }
}

// ===================== router top-8 =====================
__global__ __launch_bounds__(256) void topk_k(const float* __restrict__ logits,
                                              int* __restrict__ idx,
                                              float* __restrict__ wts) {
    int t = blockIdx.x * 8 + (threadIdx.x >> 5);
    int lane = threadIdx.x & 31;
    if (t >= T_TOK) return;
    const float* lr = logits + (size_t)t * NE;
    float v0 = lr[lane], v1 = lr[lane + 32];
    float selv[TOPK];
    int seli[TOPK];
    for (int s = 0; s < TOPK; s++) {
        float bv = v0;
        int bi = lane;
        if (v1 > bv) { bv = v1; bi = lane + 32; }
        for (int off = 16; off > 0; off >>= 1) {
            float ov = __shfl_xor_sync(0xffffffffu, bv, off);
            int oi = __shfl_xor_sync(0xffffffffu, bi, off);
            if (ov > bv || (ov == bv && oi < bi)) { bv = ov; bi = oi; }
        }
        selv[s] = bv;
        seli[s] = bi;
        if (bi == lane) v0 = -1e30f;
        if (bi == lane + 32) v1 = -1e30f;
    }
    if (lane == 0) {
        float mx = selv[0];
        float e[TOPK], sum = 0.f;
        for (int s = 0; s < TOPK; s++) { e[s] = __expf(selv[s] - mx); sum += e[s]; }
        float inv = 1.f / sum;
        for (int s = 0; s < TOPK; s++) {
            idx[t * TOPK + s] = seli[s];
            wts[t * TOPK + s] = e[s] * inv;
        }
    }
}

// ===================== routing plumbing =====================
__global__ void zero64_k(int* c) { if (threadIdx.x < NE) c[threadIdx.x] = 0; }

__global__ void count_k(const int* __restrict__ idx, int* __restrict__ counts) {
    int i = blockIdx.x * blockDim.x + threadIdx.x;
    if (i < T_TOK * TOPK) atomicAdd(&counts[idx[i]], 1);
}

__global__ void scan_k(const int* __restrict__ counts, int* __restrict__ off,
                       int* __restrict__ cursor) {
    if (threadIdx.x == 0) {
        int s = 0;
        for (int e = 0; e < NE; e++) { off[e] = s; cursor[e] = s; s += counts[e]; }
        off[NE] = s;
    }
}

__global__ void fill_k(const int* __restrict__ idx, const float* __restrict__ wts,
                       int* __restrict__ cursor, int* __restrict__ tok,
                       int* __restrict__ crow, float* __restrict__ rsc) {
    int i = blockIdx.x * blockDim.x + threadIdx.x;
    if (i < T_TOK * TOPK) {
        int t = i >> 3;
        int e = idx[i];
        int p = atomicAdd(&cursor[e], 1);
        tok[p] = t;
        crow[p] = i;
        rsc[p] = wts[i];
    }
}

// ===================== silu(g)*u -> split bf16 act =====================
__global__ void silumul_split_k(const float* __restrict__ gu,
                                bf16* __restrict__ ahi, bf16* __restrict__ alo) {
    int i = blockIdx.x * blockDim.x + threadIdx.x;
    if (i < NROWS * FF) {
        int r = i / FF, j = i - r * FF;
        float g = gu[(size_t)r * GU_N + j];
        float u = gu[(size_t)r * GU_N + FF + j];
        float a = (g / (1.f + __expf(-g))) * u;
        bf16 h, l;
        split_bf16(a, h, l);
        ahi[i] = h;
        alo[i] = l;
    }
}

// ===================== combine 8 slots =====================
__global__ void combine_k(const float* __restrict__ part, float* __restrict__ out) {
    int i = blockIdx.x * blockDim.x + threadIdx.x;
    if (i < T_TOK * D_DIM) {
        int t = i >> 11;
        int d = i & 2047;
        float s = 0.f;
#pragma unroll
        for (int sl = 0; sl < TOPK; sl++)
            s += part[((size_t)(t * TOPK + sl)) * D_DIM + d];
        out[i] = s;
    }
}

// ===================== launch =====================
extern "C" void kernel_launch(void* const* d_in, const int* in_sizes, int n_in,
                              void* d_out, int out_size) {
    const int*   positions = (const int*)d_in[0];
    const float* hidden    = (const float*)d_in[1];
    const float* in_ln     = (const float*)d_in[2];
    const float* post_ln   = (const float*)d_in[3];
    const float* qns       = (const float*)d_in[4];
    const float* kns       = (const float*)d_in[5];
    const float* wq        = (const float*)d_in[6];
    const float* wk        = (const float*)d_in[7];
    const float* wv        = (const float*)d_in[8];
    const float* wo        = (const float*)d_in[9];
    const float* wr        = (const float*)d_in[10];
    const float* wg        = (const float*)d_in[11];
    const float* wu        = (const float*)d_in[12];
    const float* wd        = (const float*)d_in[13];

    float* outp   = (float*)d_out;
    float* residp = outp + (size_t)T_TOK * D_DIM;

    cudaFuncSetAttribute(mma_gemm_k, cudaFuncAttributeMaxDynamicSharedMemorySize, MMA_SMEM);
    cudaFuncSetAttribute(fattn_k, cudaFuncAttributeMaxDynamicSharedMemorySize, ATT_SMEM);

    bf16 *hn_hi, *hn_lo, *qh, *ql, *kh, *kl, *vth, *vtl;
    bf16 *ao_hi, *ao_lo, *h2n_hi, *h2n_lo, *act_hi, *act_lo;
    float *qkv, *logits, *twt, *rsc, *gu, *part;
    int *tidx, *counts, *off, *cursor, *tok, *crow;
    cudaGetSymbolAddress((void**)&hn_hi, g_hn_hi);
    cudaGetSymbolAddress((void**)&hn_lo, g_hn_lo);
    cudaGetSymbolAddress((void**)&qkv, g_qkv);
    cudaGetSymbolAddress((void**)&qh, g_qh);
    cudaGetSymbolAddress((void**)&ql, g_ql);
    cudaGetSymbolAddress((void**)&kh, g_kh);
    cudaGetSymbolAddress((void**)&kl, g_kl);
    cudaGetSymbolAddress((void**)&vth, g_vth);
    cudaGetSymbolAddress((void**)&vtl, g_vtl);
    cudaGetSymbolAddress((void**)&ao_hi, g_ao_hi);
    cudaGetSymbolAddress((void**)&ao_lo, g_ao_lo);
    cudaGetSymbolAddress((void**)&h2n_hi, g_h2n_hi);
    cudaGetSymbolAddress((void**)&h2n_lo, g_h2n_lo);
    cudaGetSymbolAddress((void**)&logits, g_logits);
    cudaGetSymbolAddress((void**)&tidx, g_tidx);
    cudaGetSymbolAddress((void**)&twt, g_twt);
    cudaGetSymbolAddress((void**)&counts, g_counts);
    cudaGetSymbolAddress((void**)&off, g_off);
    cudaGetSymbolAddress((void**)&cursor, g_cursor);
    cudaGetSymbolAddress((void**)&tok, g_tok);
    cudaGetSymbolAddress((void**)&crow, g_crow);
    cudaGetSymbolAddress((void**)&rsc, g_rsc);
    cudaGetSymbolAddress((void**)&gu, g_gu);
    cudaGetSymbolAddress((void**)&act_hi, g_act_hi);
    cudaGetSymbolAddress((void**)&act_lo, g_act_lo);
    cudaGetSymbolAddress((void**)&part, g_part);

    // 1. pre-attention rmsnorm (split only)
    rmsnorm_split_k<<<T_TOK, 256>>>(hidden, in_ln, hn_hi, hn_lo);

    // 2. merged Q/K/V projection: 32 Q-tiles + 4 K + 4 V = 40 x 16 = 640 blocks
    mma_gemm_k<<<dim3(40, T_TOK/128, 1), 256, MMA_SMEM>>>(
        hn_hi, hn_lo, wq, wk, wv, 32, 4, HQ*HD, HKV*HD, HKV*HD, 0, 128,
        qkv, QKV_N, T_TOK, D_DIM,
        nullptr, nullptr, nullptr, nullptr, nullptr);

    // 3. QK rmsnorm + rope -> split bf16; V transpose + split
    qknorm_rope_split_k<<<dim3(T_TOK, HQ + HKV), 128>>>(qkv, qns, kns, positions,
                                                        qh, ql, kh, kl);
    vtrans_split_k<<<dim3(T_TOK/32, HD/32, HKV), 256>>>(qkv, vth, vtl);

    // 4. MMA flash attention
    fattn_k<<<dim3(T_TOK/128, HQ), 256, ATT_SMEM>>>(qh, ql, kh, kl, vth, vtl,
                                                    ao_hi, ao_lo);

    // 5. O projection + residual
    mma_gemm_k<<<dim3(D_DIM/128, T_TOK/128, 1), 256, MMA_SMEM>>>(
        ao_hi, ao_lo, wo, nullptr, nullptr, 16, 0, D_DIM, 0, 0, 0, 128,
        residp, D_DIM, T_TOK, HQ*HD,
        nullptr, nullptr, nullptr, nullptr, hidden);

    // 6. post-attention rmsnorm (split only; router consumes split form)
    rmsnorm_split_k<<<T_TOK, 256>>>(residp, post_ln, h2n_hi, h2n_lo);

    // 7. router logits via MMA (N=64 guard) + top-8
    mma_gemm_k<<<dim3(1, T_TOK/128, 1), 256, MMA_SMEM>>>(
        h2n_hi, h2n_lo, wr, nullptr, nullptr, 1, 0, NE, 0, 0, 0, 64,
        logits, NE, T_TOK, D_DIM,
        nullptr, nullptr, nullptr, nullptr, nullptr);
    topk_k<<<T_TOK / 8, 256>>>(logits, tidx, twt);

    // 8. per-expert token lists
    zero64_k<<<1, 64>>>(counts);
    count_k<<<(T_TOK * TOPK + 255) / 256, 256>>>(tidx, counts);
    scan_k<<<1, 32>>>(counts, off, cursor);
    fill_k<<<(T_TOK * TOPK + 255) / 256, 256>>>(tidx, twt, cursor, tok, crow, rsc);

    // 9. merged gate+up gather-GEMM per expert: 6+6 tiles x 16 x 64
    mma_gemm_k<<<dim3(12, 16, NE), 256, MMA_SMEM>>>(
        h2n_hi, h2n_lo, wg, wu, nullptr, 6, 6, FF, FF, 0, (size_t)D_DIM*FF, 128,
        gu, GU_N, T_TOK, D_DIM,
        off, tok, nullptr, nullptr, nullptr);

    // 10. silu(g)*u split
    silumul_split_k<<<(NROWS * FF + 255) / 256, 256>>>(gu, act_hi, act_lo);

    // 11. down scatter-GEMM per expert
    mma_gemm_k<<<dim3(D_DIM/128, 16, NE), 256, MMA_SMEM>>>(
        act_hi, act_lo, wd, nullptr, nullptr, 16, 0, D_DIM, 0, 0, (size_t)FF*D_DIM, 128,
        part, D_DIM, T_TOK, FF,
        off, nullptr, crow, rsc, nullptr);

    // 12. combine
    combine_k<<<(T_TOK * D_DIM + 255) / 256, 256>>>(part, outp);
}